// round 1
// baseline (speedup 1.0000x reference)
#include <cuda_runtime.h>
#include <math.h>

#define TT 4
#define BB 2
#define TB 8
#define NN 1024
#define CC 256
#define HH 8
#define DD 32
#define CN (CC*NN)        // 262144
#define TBCN (TB*CN)      // 2097152

// Scratch (static device globals: no allocations allowed)
__device__ float g_tmp[TBCN];       // query + query_pos (flat)
__device__ float g_qkv[3*TBCN];     // spiked branch outputs q,k,v (TB,C,N) each
__device__ float g_os[TBCN];        // spiked attention output (TB,C,N)
__device__ float g_wp[4*CC*CC];     // BN-folded weights
__device__ float g_bp[4*CC];        // BN-folded biases

// MultiSpike_norm4: round(clamp(x,0,4))/4 ; jnp.round = round-half-to-even = rintf
__device__ __forceinline__ float spikef(float v){
    v = fminf(fmaxf(v, 0.0f), 4.0f);
    return rintf(v) * 0.25f;
}

// ---------------------------------------------------------------------------
// Fold BN into conv weights: W'[i,o,c] = W*g/sqrt(var+eps); b' likewise.
// ---------------------------------------------------------------------------
__global__ void fold_weights_kernel(const float* __restrict__ w,
                                    const float* __restrict__ b,
                                    const float* __restrict__ gam,
                                    const float* __restrict__ beta,
                                    const float* __restrict__ mean,
                                    const float* __restrict__ var)
{
    int idx = blockIdx.x * blockDim.x + threadIdx.x;   // 4*C*C threads
    int oc = idx >> 8;                                 // i*C + o
    float inv = gam[oc] * rsqrtf(var[oc] + 1e-5f);
    g_wp[idx] = w[idx] * inv;
    if (idx < 4*CC){
        float invb = gam[idx] * rsqrtf(var[idx] + 1e-5f);
        g_bp[idx] = (b[idx] - mean[idx]) * invb + beta[idx];
    }
}

// ---------------------------------------------------------------------------
// tmp = query + query_pos (flat). Spike is applied at GEMM load time.
// ---------------------------------------------------------------------------
__global__ void prep_kernel(const float4* __restrict__ q, const float4* __restrict__ qp)
{
    int i = blockIdx.x * blockDim.x + threadIdx.x;     // TBCN/4 threads
    float4 a = q[i], c = qp[i];
    reinterpret_cast<float4*>(g_tmp)[i] =
        make_float4(a.x + c.x, a.y + c.y, a.z + c.z, a.w + c.w);
}

// ---------------------------------------------------------------------------
// QKV GEMM: for each tb, Y[m,n] = spike( sum_k Wqkv'[m,k]*spike(tmp[tb,k,n]) + b'[m] )
// M=768 (3 stacked branches), K=256, N=1024. Tile 64x64x16, 4x4/thread.
// ---------------------------------------------------------------------------
__global__ void __launch_bounds__(256) qkv_gemm_kernel()
{
    const int tb = blockIdx.z;
    const int bm = blockIdx.y * 64;
    const int bn = blockIdx.x * 64;
    __shared__ float As[16][64];
    __shared__ float Bs[16][64];
    const int tid = threadIdx.x;
    const int tx = tid & 15, ty = tid >> 4;
    const int am = tid >> 2, ak = (tid & 3) << 2;
    const int br = tid >> 4, bc = (tid & 15) << 2;
    const float* wptr = g_wp + (bm + am)*CC + ak;
    const float* xptr = g_tmp + tb*CN + br*NN + bn + bc;
    float acc[4][4] = {};
    for (int k0 = 0; k0 < CC; k0 += 16){
        float4 a = *reinterpret_cast<const float4*>(wptr + k0);
        As[ak+0][am] = a.x; As[ak+1][am] = a.y; As[ak+2][am] = a.z; As[ak+3][am] = a.w;
        float4 bv = *reinterpret_cast<const float4*>(xptr + k0*NN);
        bv.x = spikef(bv.x); bv.y = spikef(bv.y); bv.z = spikef(bv.z); bv.w = spikef(bv.w);
        *reinterpret_cast<float4*>(&Bs[br][bc]) = bv;
        __syncthreads();
#pragma unroll
        for (int kk = 0; kk < 16; kk++){
            float4 av = *reinterpret_cast<const float4*>(&As[kk][ty<<2]);
            float4 bb = *reinterpret_cast<const float4*>(&Bs[kk][tx<<2]);
            acc[0][0] += av.x*bb.x; acc[0][1] += av.x*bb.y; acc[0][2] += av.x*bb.z; acc[0][3] += av.x*bb.w;
            acc[1][0] += av.y*bb.x; acc[1][1] += av.y*bb.y; acc[1][2] += av.y*bb.z; acc[1][3] += av.y*bb.w;
            acc[2][0] += av.z*bb.x; acc[2][1] += av.z*bb.y; acc[2][2] += av.z*bb.z; acc[2][3] += av.z*bb.w;
            acc[3][0] += av.w*bb.x; acc[3][1] += av.w*bb.y; acc[3][2] += av.w*bb.z; acc[3][3] += av.w*bb.w;
        }
        __syncthreads();
    }
#pragma unroll
    for (int i = 0; i < 4; i++){
        int gm = bm + (ty<<2) + i;            // [0,768)
        float bs = g_bp[gm];
        int branch = gm >> 8;
        int c = gm & 255;
        float4 r;
        r.x = spikef(acc[i][0] + bs);
        r.y = spikef(acc[i][1] + bs);
        r.z = spikef(acc[i][2] + bs);
        r.w = spikef(acc[i][3] + bs);
        *reinterpret_cast<float4*>(&g_qkv[branch*TBCN + tb*CN + c*NN + bn + (tx<<2)]) = r;
    }
}

// ---------------------------------------------------------------------------
// Attention per (tb,h): M[e,d] = sum_n K[e,n]V[d,n] (D x D), then
// O[d,n] = spike( SCALE * sum_e Q[e,n] M[e,d] ).  64 blocks x 256 threads.
// ---------------------------------------------------------------------------
__global__ void __launch_bounds__(256) attn_kernel()
{
    const float* Q = g_qkv;
    const float* K = g_qkv + TBCN;
    const float* V = g_qkv + 2*TBCN;
    const int tb = blockIdx.x >> 3;
    const int h  = blockIdx.x & 7;
    const int cbase = tb*CN + h*DD*NN;
    __shared__ float Ks[32][132];
    __shared__ float Vs[32][132];
    __shared__ float Ms[32][32];
    const int tid = threadIdx.x;
    const int lr = tid >> 5;            // warp id: row group for tile loads
    const int c4 = (tid & 31) << 2;     // col within tile load
    const int e0 = tid >> 4;            // row pair (e0, e0+16)
    const int d0 = tid & 15;            // row pair (d0, d0+16)
    float m00=0.f, m01=0.f, m10=0.f, m11=0.f;

    for (int ch = 0; ch < 8; ch++){
        const int nb = ch << 7;
#pragma unroll
        for (int r = lr; r < 32; r += 8){
            *reinterpret_cast<float4*>(&Ks[r][c4]) =
                *reinterpret_cast<const float4*>(&K[cbase + r*NN + nb + c4]);
            *reinterpret_cast<float4*>(&Vs[r][c4]) =
                *reinterpret_cast<const float4*>(&V[cbase + r*NN + nb + c4]);
        }
        __syncthreads();
#pragma unroll
        for (int n = 0; n < 128; n += 4){
            float4 ka = *reinterpret_cast<const float4*>(&Ks[e0][n]);
            float4 kb = *reinterpret_cast<const float4*>(&Ks[e0+16][n]);
            float4 va = *reinterpret_cast<const float4*>(&Vs[d0][n]);
            float4 vb = *reinterpret_cast<const float4*>(&Vs[d0+16][n]);
            m00 += ka.x*va.x + ka.y*va.y + ka.z*va.z + ka.w*va.w;
            m01 += ka.x*vb.x + ka.y*vb.y + ka.z*vb.z + ka.w*vb.w;
            m10 += kb.x*va.x + kb.y*va.y + kb.z*va.z + kb.w*va.w;
            m11 += kb.x*vb.x + kb.y*vb.y + kb.z*vb.z + kb.w*vb.w;
        }
        __syncthreads();
    }
    Ms[e0][d0]      = m00; Ms[e0][d0+16]    = m01;
    Ms[e0+16][d0]   = m10; Ms[e0+16][d0+16] = m11;
    __syncthreads();

    const int dd = tid >> 4;            // output row pair (dd, dd+16)
    const int n0 = (tid & 15) << 2;     // col groups n0 and n0+64
    for (int ch = 0; ch < 8; ch++){
        const int nb = ch << 7;
#pragma unroll
        for (int r = lr; r < 32; r += 8){
            *reinterpret_cast<float4*>(&Ks[r][c4]) =
                *reinterpret_cast<const float4*>(&Q[cbase + r*NN + nb + c4]);
        }
        __syncthreads();
        float4 o00 = make_float4(0,0,0,0), o01 = make_float4(0,0,0,0);
        float4 o10 = make_float4(0,0,0,0), o11 = make_float4(0,0,0,0);
#pragma unroll
        for (int e = 0; e < 32; e++){
            float w0 = Ms[e][dd];
            float w1 = Ms[e][dd+16];
            float4 qa = *reinterpret_cast<const float4*>(&Ks[e][n0]);
            float4 qb = *reinterpret_cast<const float4*>(&Ks[e][n0+64]);
            o00.x += w0*qa.x; o00.y += w0*qa.y; o00.z += w0*qa.z; o00.w += w0*qa.w;
            o01.x += w0*qb.x; o01.y += w0*qb.y; o01.z += w0*qb.z; o01.w += w0*qb.w;
            o10.x += w1*qa.x; o10.y += w1*qa.y; o10.z += w1*qa.z; o10.w += w1*qa.w;
            o11.x += w1*qb.x; o11.y += w1*qb.y; o11.z += w1*qb.z; o11.w += w1*qb.w;
        }
        float4 s;
        s = make_float4(spikef(0.1f*o00.x), spikef(0.1f*o00.y), spikef(0.1f*o00.z), spikef(0.1f*o00.w));
        *reinterpret_cast<float4*>(&g_os[cbase + dd*NN + nb + n0]) = s;
        s = make_float4(spikef(0.1f*o01.x), spikef(0.1f*o01.y), spikef(0.1f*o01.z), spikef(0.1f*o01.w));
        *reinterpret_cast<float4*>(&g_os[cbase + dd*NN + nb + n0 + 64]) = s;
        s = make_float4(spikef(0.1f*o10.x), spikef(0.1f*o10.y), spikef(0.1f*o10.z), spikef(0.1f*o10.w));
        *reinterpret_cast<float4*>(&g_os[cbase + (dd+16)*NN + nb + n0]) = s;
        s = make_float4(spikef(0.1f*o11.x), spikef(0.1f*o11.y), spikef(0.1f*o11.z), spikef(0.1f*o11.w));
        *reinterpret_cast<float4*>(&g_os[cbase + (dd+16)*NN + nb + n0 + 64]) = s;
        __syncthreads();
    }
}

// ---------------------------------------------------------------------------
// Projection GEMM + residual: out = W3'*Os + b3' + tmp   (flat layouts match)
// ---------------------------------------------------------------------------
__global__ void __launch_bounds__(256) proj_gemm_kernel(float* __restrict__ out)
{
    const int tb = blockIdx.z;
    const int bm = blockIdx.y * 64;
    const int bn = blockIdx.x * 64;
    __shared__ float As[16][64];
    __shared__ float Bs[16][64];
    const int tid = threadIdx.x;
    const int tx = tid & 15, ty = tid >> 4;
    const int am = tid >> 2, ak = (tid & 3) << 2;
    const int br = tid >> 4, bc = (tid & 15) << 2;
    const float* wptr = g_wp + (768 + bm + am)*CC + ak;
    const float* xptr = g_os + tb*CN + br*NN + bn + bc;
    float acc[4][4] = {};
    for (int k0 = 0; k0 < CC; k0 += 16){
        float4 a = *reinterpret_cast<const float4*>(wptr + k0);
        As[ak+0][am] = a.x; As[ak+1][am] = a.y; As[ak+2][am] = a.z; As[ak+3][am] = a.w;
        *reinterpret_cast<float4*>(&Bs[br][bc]) =
            *reinterpret_cast<const float4*>(xptr + k0*NN);
        __syncthreads();
#pragma unroll
        for (int kk = 0; kk < 16; kk++){
            float4 av = *reinterpret_cast<const float4*>(&As[kk][ty<<2]);
            float4 bb = *reinterpret_cast<const float4*>(&Bs[kk][tx<<2]);
            acc[0][0] += av.x*bb.x; acc[0][1] += av.x*bb.y; acc[0][2] += av.x*bb.z; acc[0][3] += av.x*bb.w;
            acc[1][0] += av.y*bb.x; acc[1][1] += av.y*bb.y; acc[1][2] += av.y*bb.z; acc[1][3] += av.y*bb.w;
            acc[2][0] += av.z*bb.x; acc[2][1] += av.z*bb.y; acc[2][2] += av.z*bb.z; acc[2][3] += av.z*bb.w;
            acc[3][0] += av.w*bb.x; acc[3][1] += av.w*bb.y; acc[3][2] += av.w*bb.z; acc[3][3] += av.w*bb.w;
        }
        __syncthreads();
    }
#pragma unroll
    for (int i = 0; i < 4; i++){
        int gm = bm + (ty<<2) + i;            // [0,256)
        float bs = g_bp[768 + gm];
        int idx = tb*CN + gm*NN + bn + (tx<<2);
        float4 ad = *reinterpret_cast<const float4*>(&g_tmp[idx]);
        float4 r;
        r.x = acc[i][0] + bs + ad.x;
        r.y = acc[i][1] + bs + ad.y;
        r.z = acc[i][2] + bs + ad.z;
        r.w = acc[i][3] + bs + ad.w;
        *reinterpret_cast<float4*>(&out[idx]) = r;
    }
}

// ---------------------------------------------------------------------------
extern "C" void kernel_launch(void* const* d_in, const int* in_sizes, int n_in,
                              void* d_out, int out_size)
{
    const float* q    = (const float*)d_in[0];
    // d_in[1] (key) and d_in[2] (value) are unused by the reference
    const float* qp   = (const float*)d_in[3];
    const float* w    = (const float*)d_in[4];
    const float* b    = (const float*)d_in[5];
    const float* gam  = (const float*)d_in[6];
    const float* bet  = (const float*)d_in[7];
    const float* mean = (const float*)d_in[8];
    const float* var  = (const float*)d_in[9];
    float* out = (float*)d_out;

    fold_weights_kernel<<<(4*CC*CC)/256, 256>>>(w, b, gam, bet, mean, var);
    prep_kernel<<<(TBCN/4)/256, 256>>>((const float4*)q, (const float4*)qp);

    dim3 gq(NN/64, 768/64, TB);   // 16 x 12 x 8
    qkv_gemm_kernel<<<gq, 256>>>();

    attn_kernel<<<64, 256>>>();

    dim3 gp(NN/64, CC/64, TB);    // 16 x 4 x 8
    proj_gemm_kernel<<<gp, 256>>>(out);
}

// round 2
// speedup vs baseline: 1.3938x; 1.3938x over previous
#include <cuda_runtime.h>
#include <math.h>

#define TT 4
#define BB 2
#define TB 8
#define NN 1024
#define CC 256
#define HH 8
#define DD 32
#define CN (CC*NN)        // 262144
#define TBCN (TB*CN)      // 2097152

// Scratch (static device globals: no allocations allowed)
__device__ float g_tmp[TBCN];       // query + query_pos (flat)
__device__ float g_qkv[3*TBCN];     // spiked branch outputs q,k,v (TB,C,N) each
__device__ float g_os[TBCN];        // spiked attention output (TB,C,N)
__device__ float g_M[64*DD*DD];     // per-(tb,h) K^T V accumulators (32x32 each)
__device__ float g_wp[4*CC*CC];     // BN-folded weights
__device__ float g_bp[4*CC];        // BN-folded biases

// MultiSpike_norm4: round(clamp(x,0,4))/4 ; jnp.round = round-half-to-even = rintf
__device__ __forceinline__ float spikef(float v){
    v = fminf(fmaxf(v, 0.0f), 4.0f);
    return rintf(v) * 0.25f;
}

// ---------------------------------------------------------------------------
// Fold BN into conv weights: W'[i,o,c] = W*g/sqrt(var+eps); b' likewise.
// ---------------------------------------------------------------------------
__global__ void fold_weights_kernel(const float* __restrict__ w,
                                    const float* __restrict__ b,
                                    const float* __restrict__ gam,
                                    const float* __restrict__ beta,
                                    const float* __restrict__ mean,
                                    const float* __restrict__ var)
{
    int idx = blockIdx.x * blockDim.x + threadIdx.x;   // 4*C*C threads
    int oc = idx >> 8;                                 // i*C + o
    float inv = gam[oc] * rsqrtf(var[oc] + 1e-5f);
    g_wp[idx] = w[idx] * inv;
    if (idx < 4*CC){
        float invb = gam[idx] * rsqrtf(var[idx] + 1e-5f);
        g_bp[idx] = (b[idx] - mean[idx]) * invb + beta[idx];
    }
}

// ---------------------------------------------------------------------------
// tmp = query + query_pos (flat). Also zero the g_M accumulators.
// ---------------------------------------------------------------------------
__global__ void prep_kernel(const float4* __restrict__ q, const float4* __restrict__ qp)
{
    int i = blockIdx.x * blockDim.x + threadIdx.x;     // TBCN/4 threads
    float4 a = q[i], c = qp[i];
    reinterpret_cast<float4*>(g_tmp)[i] =
        make_float4(a.x + c.x, a.y + c.y, a.z + c.z, a.w + c.w);
    if (i < (64*DD*DD)/4)
        reinterpret_cast<float4*>(g_M)[i] = make_float4(0.f,0.f,0.f,0.f);
}

// ---------------------------------------------------------------------------
// 128x128 tile SGEMM, 8x8 per thread, K-step 8, register prefetch.
// qkv: M=768 (3 stacked branches), spike(B-load), spike(bias+out) -> g_qkv.
// ---------------------------------------------------------------------------
__global__ void __launch_bounds__(256, 2) qkv_gemm_kernel()
{
    const int tb = blockIdx.z;
    const int bm = blockIdx.y * 128;
    const int bn = blockIdx.x * 128;
    __shared__ float As[8][132];
    __shared__ float Bs[8][128];
    const int tid = threadIdx.x;
    const int am = tid >> 1;              // 0..127 (A row within tile)
    const int ak = (tid & 1) << 2;        // 0 or 4
    const int bk = tid >> 5;              // 0..7
    const int bc = (tid & 31) << 2;       // 0..124
    const int tm4 = (tid >> 4) << 2;      // 0..60
    const int tn4 = (tid & 15) << 2;      // 0..60
    const float* wptr = g_wp + (bm + am)*CC + ak;
    const float* xptr = g_tmp + tb*CN + bk*NN + bn + bc;

    float acc[8][8];
#pragma unroll
    for (int i = 0; i < 8; i++)
#pragma unroll
        for (int j = 0; j < 8; j++) acc[i][j] = 0.f;

    float4 pa = *reinterpret_cast<const float4*>(wptr);
    float4 pb = *reinterpret_cast<const float4*>(xptr);
    pb.x = spikef(pb.x); pb.y = spikef(pb.y); pb.z = spikef(pb.z); pb.w = spikef(pb.w);

    for (int kt = 0; kt < 32; kt++){
        As[ak+0][am] = pa.x; As[ak+1][am] = pa.y; As[ak+2][am] = pa.z; As[ak+3][am] = pa.w;
        *reinterpret_cast<float4*>(&Bs[bk][bc]) = pb;
        __syncthreads();
        if (kt < 31){
            pa = *reinterpret_cast<const float4*>(wptr + (kt+1)*8);
            pb = *reinterpret_cast<const float4*>(xptr + (kt+1)*8*NN);
            pb.x = spikef(pb.x); pb.y = spikef(pb.y); pb.z = spikef(pb.z); pb.w = spikef(pb.w);
        }
#pragma unroll
        for (int k = 0; k < 8; k++){
            float4 a0 = *reinterpret_cast<const float4*>(&As[k][tm4]);
            float4 a1 = *reinterpret_cast<const float4*>(&As[k][64+tm4]);
            float4 b0 = *reinterpret_cast<const float4*>(&Bs[k][tn4]);
            float4 b1 = *reinterpret_cast<const float4*>(&Bs[k][64+tn4]);
            float av[8] = {a0.x,a0.y,a0.z,a0.w,a1.x,a1.y,a1.z,a1.w};
            float bv[8] = {b0.x,b0.y,b0.z,b0.w,b1.x,b1.y,b1.z,b1.w};
#pragma unroll
            for (int i = 0; i < 8; i++)
#pragma unroll
                for (int j = 0; j < 8; j++) acc[i][j] += av[i]*bv[j];
        }
        __syncthreads();
    }

#pragma unroll
    for (int i = 0; i < 8; i++){
        int gm = bm + ((i < 4) ? (tm4 + i) : (64 + tm4 + i - 4));   // [0,768)
        float bs = g_bp[gm];
        int branch = gm >> 8;
        int c = gm & 255;
        float* op = &g_qkv[branch*TBCN + tb*CN + c*NN + bn];
        float4 r;
        r.x = spikef(acc[i][0] + bs); r.y = spikef(acc[i][1] + bs);
        r.z = spikef(acc[i][2] + bs); r.w = spikef(acc[i][3] + bs);
        *reinterpret_cast<float4*>(op + tn4) = r;
        r.x = spikef(acc[i][4] + bs); r.y = spikef(acc[i][5] + bs);
        r.z = spikef(acc[i][6] + bs); r.w = spikef(acc[i][7] + bs);
        *reinterpret_cast<float4*>(op + 64 + tn4) = r;
    }
}

// ---------------------------------------------------------------------------
// Attention phase 1: partial M[e,d] += sum_{n in chunk} K[e,n]V[d,n].
// grid 512 = 64 heads x 8 n-chunks. Exact atomics (all values multiples of 1/16).
// ---------------------------------------------------------------------------
__global__ void __launch_bounds__(256) kv_kernel()
{
    const float* K = g_qkv + TBCN;
    const float* V = g_qkv + 2*TBCN;
    const int hh = blockIdx.x >> 3;      // 0..63
    const int nb = (blockIdx.x & 7) << 7;
    const int cbase = hh * (DD*NN);
    __shared__ float Ks[32][132];
    __shared__ float Vs[32][132];
    const int tid = threadIdx.x;
    const int lr = tid >> 5;
    const int c4 = (tid & 31) << 2;
#pragma unroll
    for (int r = lr; r < 32; r += 8){
        *reinterpret_cast<float4*>(&Ks[r][c4]) =
            *reinterpret_cast<const float4*>(&K[cbase + r*NN + nb + c4]);
        *reinterpret_cast<float4*>(&Vs[r][c4]) =
            *reinterpret_cast<const float4*>(&V[cbase + r*NN + nb + c4]);
    }
    __syncthreads();
    const int e0 = tid >> 4;
    const int d0 = tid & 15;
    float m00=0.f, m01=0.f, m10=0.f, m11=0.f;
#pragma unroll
    for (int n = 0; n < 128; n += 4){
        float4 ka = *reinterpret_cast<const float4*>(&Ks[e0][n]);
        float4 kb = *reinterpret_cast<const float4*>(&Ks[e0+16][n]);
        float4 va = *reinterpret_cast<const float4*>(&Vs[d0][n]);
        float4 vb = *reinterpret_cast<const float4*>(&Vs[d0+16][n]);
        m00 += ka.x*va.x + ka.y*va.y + ka.z*va.z + ka.w*va.w;
        m01 += ka.x*vb.x + ka.y*vb.y + ka.z*vb.z + ka.w*vb.w;
        m10 += kb.x*va.x + kb.y*va.y + kb.z*va.z + kb.w*va.w;
        m11 += kb.x*vb.x + kb.y*vb.y + kb.z*vb.z + kb.w*vb.w;
    }
    float* M = g_M + hh*DD*DD;
    atomicAdd(&M[e0*DD + d0],           m00);
    atomicAdd(&M[e0*DD + d0 + 16],      m01);
    atomicAdd(&M[(e0+16)*DD + d0],      m10);
    atomicAdd(&M[(e0+16)*DD + d0 + 16], m11);
}

// ---------------------------------------------------------------------------
// Attention phase 2: O[d,n] = spike(0.1 * sum_e Q[e,n] M[e,d]).
// grid 512 = 64 heads x 8 n-chunks.
// ---------------------------------------------------------------------------
__global__ void __launch_bounds__(256) qm_kernel()
{
    const float* Q = g_qkv;
    const int hh = blockIdx.x >> 3;
    const int nb = (blockIdx.x & 7) << 7;
    const int cbase = hh * (DD*NN);
    __shared__ float Qs[32][132];
    __shared__ float Ms[32][32];
    const int tid = threadIdx.x;
    const int lr = tid >> 5;
    const int c4 = (tid & 31) << 2;
    if (tid < 256){
        float4 mv = reinterpret_cast<const float4*>(g_M + hh*DD*DD)[tid];
        *reinterpret_cast<float4*>(&Ms[tid >> 3][(tid & 7) << 2]) = mv;
    }
#pragma unroll
    for (int r = lr; r < 32; r += 8){
        *reinterpret_cast<float4*>(&Qs[r][c4]) =
            *reinterpret_cast<const float4*>(&Q[cbase + r*NN + nb + c4]);
    }
    __syncthreads();
    const int dd = tid >> 4;             // row pair (dd, dd+16)
    const int n0 = (tid & 15) << 2;      // col groups n0 and n0+64
    float4 o00 = make_float4(0,0,0,0), o01 = make_float4(0,0,0,0);
    float4 o10 = make_float4(0,0,0,0), o11 = make_float4(0,0,0,0);
#pragma unroll
    for (int e = 0; e < 32; e++){
        float w0 = Ms[e][dd];
        float w1 = Ms[e][dd+16];
        float4 qa = *reinterpret_cast<const float4*>(&Qs[e][n0]);
        float4 qb = *reinterpret_cast<const float4*>(&Qs[e][n0+64]);
        o00.x += w0*qa.x; o00.y += w0*qa.y; o00.z += w0*qa.z; o00.w += w0*qa.w;
        o01.x += w0*qb.x; o01.y += w0*qb.y; o01.z += w0*qb.z; o01.w += w0*qb.w;
        o10.x += w1*qa.x; o10.y += w1*qa.y; o10.z += w1*qa.z; o10.w += w1*qa.w;
        o11.x += w1*qb.x; o11.y += w1*qb.y; o11.z += w1*qb.z; o11.w += w1*qb.w;
    }
    float4 s;
    s = make_float4(spikef(0.1f*o00.x), spikef(0.1f*o00.y), spikef(0.1f*o00.z), spikef(0.1f*o00.w));
    *reinterpret_cast<float4*>(&g_os[cbase + dd*NN + nb + n0]) = s;
    s = make_float4(spikef(0.1f*o01.x), spikef(0.1f*o01.y), spikef(0.1f*o01.z), spikef(0.1f*o01.w));
    *reinterpret_cast<float4*>(&g_os[cbase + dd*NN + nb + n0 + 64]) = s;
    s = make_float4(spikef(0.1f*o10.x), spikef(0.1f*o10.y), spikef(0.1f*o10.z), spikef(0.1f*o10.w));
    *reinterpret_cast<float4*>(&g_os[cbase + (dd+16)*NN + nb + n0]) = s;
    s = make_float4(spikef(0.1f*o11.x), spikef(0.1f*o11.y), spikef(0.1f*o11.z), spikef(0.1f*o11.w));
    *reinterpret_cast<float4*>(&g_os[cbase + (dd+16)*NN + nb + n0 + 64]) = s;
}

// ---------------------------------------------------------------------------
// Projection GEMM + residual: out = W3'*Os + b3' + tmp. 128x128 tile.
// ---------------------------------------------------------------------------
__global__ void __launch_bounds__(256, 2) proj_gemm_kernel(float* __restrict__ out)
{
    const int tb = blockIdx.z;
    const int bm = blockIdx.y * 128;
    const int bn = blockIdx.x * 128;
    __shared__ float As[8][132];
    __shared__ float Bs[8][128];
    const int tid = threadIdx.x;
    const int am = tid >> 1;
    const int ak = (tid & 1) << 2;
    const int bk = tid >> 5;
    const int bc = (tid & 31) << 2;
    const int tm4 = (tid >> 4) << 2;
    const int tn4 = (tid & 15) << 2;
    const float* wptr = g_wp + (768 + bm + am)*CC + ak;
    const float* xptr = g_os + tb*CN + bk*NN + bn + bc;

    float acc[8][8];
#pragma unroll
    for (int i = 0; i < 8; i++)
#pragma unroll
        for (int j = 0; j < 8; j++) acc[i][j] = 0.f;

    float4 pa = *reinterpret_cast<const float4*>(wptr);
    float4 pb = *reinterpret_cast<const float4*>(xptr);

    for (int kt = 0; kt < 32; kt++){
        As[ak+0][am] = pa.x; As[ak+1][am] = pa.y; As[ak+2][am] = pa.z; As[ak+3][am] = pa.w;
        *reinterpret_cast<float4*>(&Bs[bk][bc]) = pb;
        __syncthreads();
        if (kt < 31){
            pa = *reinterpret_cast<const float4*>(wptr + (kt+1)*8);
            pb = *reinterpret_cast<const float4*>(xptr + (kt+1)*8*NN);
        }
#pragma unroll
        for (int k = 0; k < 8; k++){
            float4 a0 = *reinterpret_cast<const float4*>(&As[k][tm4]);
            float4 a1 = *reinterpret_cast<const float4*>(&As[k][64+tm4]);
            float4 b0 = *reinterpret_cast<const float4*>(&Bs[k][tn4]);
            float4 b1 = *reinterpret_cast<const float4*>(&Bs[k][64+tn4]);
            float av[8] = {a0.x,a0.y,a0.z,a0.w,a1.x,a1.y,a1.z,a1.w};
            float bv[8] = {b0.x,b0.y,b0.z,b0.w,b1.x,b1.y,b1.z,b1.w};
#pragma unroll
            for (int i = 0; i < 8; i++)
#pragma unroll
                for (int j = 0; j < 8; j++) acc[i][j] += av[i]*bv[j];
        }
        __syncthreads();
    }

#pragma unroll
    for (int i = 0; i < 8; i++){
        int gm = bm + ((i < 4) ? (tm4 + i) : (64 + tm4 + i - 4));   // [0,256)
        float bs = g_bp[768 + gm];
        int base = tb*CN + gm*NN + bn;
        float4 ad = *reinterpret_cast<const float4*>(&g_tmp[base + tn4]);
        float4 r;
        r.x = acc[i][0] + bs + ad.x; r.y = acc[i][1] + bs + ad.y;
        r.z = acc[i][2] + bs + ad.z; r.w = acc[i][3] + bs + ad.w;
        *reinterpret_cast<float4*>(&out[base + tn4]) = r;
        ad = *reinterpret_cast<const float4*>(&g_tmp[base + 64 + tn4]);
        r.x = acc[i][4] + bs + ad.x; r.y = acc[i][5] + bs + ad.y;
        r.z = acc[i][6] + bs + ad.z; r.w = acc[i][7] + bs + ad.w;
        *reinterpret_cast<float4*>(&out[base + 64 + tn4]) = r;
    }
}

// ---------------------------------------------------------------------------
extern "C" void kernel_launch(void* const* d_in, const int* in_sizes, int n_in,
                              void* d_out, int out_size)
{
    const float* q    = (const float*)d_in[0];
    // d_in[1] (key) and d_in[2] (value) are unused by the reference
    const float* qp   = (const float*)d_in[3];
    const float* w    = (const float*)d_in[4];
    const float* b    = (const float*)d_in[5];
    const float* gam  = (const float*)d_in[6];
    const float* bet  = (const float*)d_in[7];
    const float* mean = (const float*)d_in[8];
    const float* var  = (const float*)d_in[9];
    float* out = (float*)d_out;

    fold_weights_kernel<<<(4*CC*CC)/256, 256>>>(w, b, gam, bet, mean, var);
    prep_kernel<<<(TBCN/4)/256, 256>>>((const float4*)q, (const float4*)qp);

    dim3 gq(NN/128, 768/128, TB);   // 8 x 6 x 8 = 384 blocks
    qkv_gemm_kernel<<<gq, 256>>>();

    kv_kernel<<<512, 256>>>();
    qm_kernel<<<512, 256>>>();

    dim3 gp(NN/128, CC/128, TB);    // 8 x 2 x 8 = 128 blocks
    proj_gemm_kernel<<<gp, 256>>>(out);
}

// round 4
// speedup vs baseline: 2.5527x; 1.8314x over previous
#include <cuda_runtime.h>
#include <cuda_fp16.h>
#include <math.h>
#include <cstdint>

#define TT 4
#define BB 2
#define TB 8
#define NN 1024
#define CC 256
#define HH 8
#define DD 32
#define CN (CC*NN)        // 262144
#define TBCN (TB*CN)      // 2097152

// ---------------------------------------------------------------------------
// Scratch (static device globals: no allocations allowed)
// ---------------------------------------------------------------------------
__device__ float g_tmp[TBCN];                       // query + query_pos (flat)
__device__ float g_qkv[3*TBCN];                     // spiked q,k,v (TB,C,N)
__device__ float g_os[TBCN];                        // spiked attention output
__device__ float g_M[64*DD*DD];                     // per-(tb,h) K^T V (32x32)
__device__ __align__(16) __half g_w16h[4*CC*CC];    // BN-folded weights hi
__device__ __align__(16) __half g_w16l[4*CC*CC];    // BN-folded weights lo
__device__ float g_bp[4*CC];                        // BN-folded biases

// MultiSpike_norm4: round(clamp(x,0,4))/4 ; jnp.round = round-half-even = rintf
__device__ __forceinline__ float spikef(float v){
    v = fminf(fmaxf(v, 0.0f), 4.0f);
    return rintf(v) * 0.25f;
}

__device__ __forceinline__ uint32_t pack2(float a, float b){
    __half2 h = __halves2half2(__float2half_rn(a), __float2half_rn(b));
    return *reinterpret_cast<uint32_t*>(&h);
}

__device__ __forceinline__ uint32_t smem_to_u32(const void* p) {
    uint32_t a;
    asm("{ .reg .u64 t; cvta.to.shared.u64 t, %1; cvt.u32.u64 %0, t; }"
        : "=r"(a) : "l"(p));
    return a;
}

// ---------------------------------------------------------------------------
// Warp MMA primitives (baseline PTX, works on .target sm_100)
// ---------------------------------------------------------------------------
__device__ __forceinline__ void ldsm_x4(uint32_t* a, uint32_t addr){
    asm volatile("ldmatrix.sync.aligned.m8n8.x4.shared.b16 {%0,%1,%2,%3}, [%4];"
        : "=r"(a[0]),"=r"(a[1]),"=r"(a[2]),"=r"(a[3]) : "r"(addr));
}
__device__ __forceinline__ void ldsm_x2_trans(uint32_t* b, uint32_t addr){
    asm volatile("ldmatrix.sync.aligned.m8n8.x2.trans.shared.b16 {%0,%1}, [%2];"
        : "=r"(b[0]),"=r"(b[1]) : "r"(addr));
}
__device__ __forceinline__ void mma16816(float* d, const uint32_t* a, const uint32_t* b){
    asm volatile("mma.sync.aligned.m16n8k16.row.col.f32.f16.f16.f32 "
        "{%0,%1,%2,%3}, {%4,%5,%6,%7}, {%8,%9}, {%0,%1,%2,%3};"
        : "+f"(d[0]),"+f"(d[1]),"+f"(d[2]),"+f"(d[3])
        : "r"(a[0]),"r"(a[1]),"r"(a[2]),"r"(a[3]), "r"(b[0]),"r"(b[1]));
}

// ---------------------------------------------------------------------------
// Fold BN into conv weights, split into fp16 hi/lo planes; fold bias.
// ---------------------------------------------------------------------------
__global__ void fold_weights_kernel(const float* __restrict__ w,
                                    const float* __restrict__ b,
                                    const float* __restrict__ gam,
                                    const float* __restrict__ beta,
                                    const float* __restrict__ mean,
                                    const float* __restrict__ var)
{
    int idx = blockIdx.x * blockDim.x + threadIdx.x;   // 4*C*C threads
    int oc = idx >> 8;                                 // i*C + o
    float inv = gam[oc] * rsqrtf(var[oc] + 1e-5f);
    float wp = w[idx] * inv;
    __half hi = __float2half_rn(wp);
    __half lo = __float2half_rn(wp - __half2float(hi));
    g_w16h[idx] = hi;
    g_w16l[idx] = lo;
    if (idx < 4*CC){
        float invb = gam[idx] * rsqrtf(var[idx] + 1e-5f);
        g_bp[idx] = (b[idx] - mean[idx]) * invb + beta[idx];
    }
}

// ---------------------------------------------------------------------------
// tmp = query + query_pos (flat). Also zero the g_M accumulators.
// ---------------------------------------------------------------------------
__global__ void prep_kernel(const float4* __restrict__ q, const float4* __restrict__ qp)
{
    int i = blockIdx.x * blockDim.x + threadIdx.x;     // TBCN/4 threads
    float4 a = q[i], c = qp[i];
    reinterpret_cast<float4*>(g_tmp)[i] =
        make_float4(a.x + c.x, a.y + c.y, a.z + c.z, a.w + c.w);
    if (i < (64*DD*DD)/4)
        reinterpret_cast<float4*>(g_M)[i] = make_float4(0.f,0.f,0.f,0.f);
}

// ---------------------------------------------------------------------------
// HMMA GEMM. Per CTA: D[m=128, n=128] = sum_k (Whi+Wlo)[m,k] * X[k,n].
// A = weights fp16 row-major [m,k] (2 planes). B = activations [k,n] (n contig),
// converted to fp16 at load (exact: spiked values have <=3 mantissa bits).
// 8 warps: 2 (m) x 4 (n); warp tile 64x32; K-chunk 64.
// MODE 0: qkv (src g_tmp, spike in+out, M=768, out g_qkv split by branch)
// MODE 1: proj (src g_os, M=256, out = D + bias + residual g_tmp)
// ---------------------------------------------------------------------------
#define AS_STRIDE 72                     // halves per A row (144B: 16-aligned, %128=16)
#define BS_STRIDE 136                    // halves per B row (272B)
#define AS_BYTES (2*128*AS_STRIDE*2)     // 36864
#define BS_BYTES (64*BS_STRIDE*2)        // 17408
#define GEMM_SMEM (AS_BYTES + BS_BYTES)  // 54272

template<int MODE>
__global__ void __launch_bounds__(256, 2) mma_gemm_kernel(float* __restrict__ out)
{
    extern __shared__ __half smem[];
    __half* As = smem;                          // [2][128][AS_STRIDE]
    __half* Bs = smem + 2*128*AS_STRIDE;        // [64][BS_STRIDE]
    const int tid  = threadIdx.x;
    const int wid  = tid >> 5;
    const int lane = tid & 31;
    const int tb = blockIdx.z;
    const int bn = blockIdx.x * 128;
    const int bm = blockIdx.y * 128;
    const int WOFF = (MODE == 0) ? 0 : 768;
    const int wm = (wid & 1) * 64;              // warp m offset
    const int wn = (wid >> 1) * 32;             // warp n offset

    float acc[16][4];
#pragma unroll
    for (int i = 0; i < 16; i++)
#pragma unroll
        for (int j = 0; j < 4; j++) acc[i][j] = 0.f;

    const float* xsrc = (MODE == 0 ? g_tmp : g_os) + tb*CN + bn;

    for (int k0 = 0; k0 < CC; k0 += 64){
        // ---- stage A (both planes), 128 rows x 64 k-halves each ----
#pragma unroll
        for (int p = 0; p < 2; p++){
            const __half* src = (p ? g_w16l : g_w16h) + (WOFF + bm)*CC + k0;
#pragma unroll
            for (int j = 0; j < 4; j++){
                int idx = tid + 256*j;          // 0..1023
                int r = idx >> 3;               // m row
                int c8 = (idx & 7) << 3;        // k offset (8 halves)
                uint4 v = *reinterpret_cast<const uint4*>(src + r*CC + c8);
                *reinterpret_cast<uint4*>(&As[(p*128 + r)*AS_STRIDE + c8]) = v;
            }
        }
        // ---- stage B: 64 k rows x 128 n, fp32 -> fp16 (+spike for MODE 0) ----
#pragma unroll
        for (int j = 0; j < 8; j++){
            int idx = tid + 256*j;              // 0..2047
            int r = idx >> 5;                   // k row
            int c4 = (idx & 31) << 2;           // n offset (4 floats)
            float4 v = *reinterpret_cast<const float4*>(xsrc + (k0 + r)*NN + c4);
            if (MODE == 0){
                v.x = spikef(v.x); v.y = spikef(v.y);
                v.z = spikef(v.z); v.w = spikef(v.w);
            }
            uint2 hv = make_uint2(pack2(v.x, v.y), pack2(v.z, v.w));
            *reinterpret_cast<uint2*>(&Bs[r*BS_STRIDE + c4]) = hv;
        }
        __syncthreads();

        // ---- compute: 4 k16 steps ----
#pragma unroll
        for (int kk = 0; kk < 64; kk += 16){
            uint32_t bf[4][2];
#pragma unroll
            for (int nt = 0; nt < 4; nt++){
                uint32_t addr = smem_to_u32(
                    &Bs[(kk + (lane & 15))*BS_STRIDE + wn + nt*8]);
                ldsm_x2_trans(bf[nt], addr);
            }
#pragma unroll
            for (int mt = 0; mt < 4; mt++){
#pragma unroll
                for (int p = 0; p < 2; p++){
                    uint32_t af[4];
                    uint32_t addr = smem_to_u32(
                        &As[(p*128 + wm + mt*16 + (lane & 15))*AS_STRIDE
                            + kk + (lane >> 4)*8]);
                    ldsm_x4(af, addr);
#pragma unroll
                    for (int nt = 0; nt < 4; nt++)
                        mma16816(acc[mt*4 + nt], af, bf[nt]);
                }
            }
        }
        __syncthreads();
    }

    // ---- epilogue ----
#pragma unroll
    for (int mt = 0; mt < 4; mt++){
#pragma unroll
        for (int nt = 0; nt < 4; nt++){
            const float* a = acc[mt*4 + nt];
            int row = wm + mt*16 + (lane >> 2);      // 0..127 (and +8)
            int col = wn + nt*8 + ((lane & 3) << 1); // 0..126, even
            if (MODE == 0){
                int gm0 = bm + row, gm1 = gm0 + 8;
                float b0 = g_bp[gm0], b1 = g_bp[gm1];
                float2 v0 = make_float2(spikef(a[0] + b0), spikef(a[1] + b0));
                float2 v1 = make_float2(spikef(a[2] + b1), spikef(a[3] + b1));
                *reinterpret_cast<float2*>(
                    &g_qkv[(gm0 >> 8)*TBCN + tb*CN + (gm0 & 255)*NN + bn + col]) = v0;
                *reinterpret_cast<float2*>(
                    &g_qkv[(gm1 >> 8)*TBCN + tb*CN + (gm1 & 255)*NN + bn + col]) = v1;
            } else {
                int gm0 = bm + row, gm1 = gm0 + 8;
                float b0 = g_bp[768 + gm0], b1 = g_bp[768 + gm1];
                int i0 = tb*CN + gm0*NN + bn + col;
                int i1 = tb*CN + gm1*NN + bn + col;
                float2 r0 = *reinterpret_cast<const float2*>(&g_tmp[i0]);
                float2 r1 = *reinterpret_cast<const float2*>(&g_tmp[i1]);
                float2 v0 = make_float2(a[0] + b0 + r0.x, a[1] + b0 + r0.y);
                float2 v1 = make_float2(a[2] + b1 + r1.x, a[3] + b1 + r1.y);
                *reinterpret_cast<float2*>(&out[i0]) = v0;
                *reinterpret_cast<float2*>(&out[i1]) = v1;
            }
        }
    }
}

// ---------------------------------------------------------------------------
// Attention phase 1: partial M[e,d] += sum_{n chunk} K[e,n]V[d,n].
// grid 512 = 64 heads x 8 n-chunks. Exact atomics (multiples of 1/16).
// ---------------------------------------------------------------------------
__global__ void __launch_bounds__(256) kv_kernel()
{
    const float* K = g_qkv + TBCN;
    const float* V = g_qkv + 2*TBCN;
    const int hh = blockIdx.x >> 3;
    const int nb = (blockIdx.x & 7) << 7;
    const int cbase = hh * (DD*NN);
    __shared__ float Ks[32][132];
    __shared__ float Vs[32][132];
    const int tid = threadIdx.x;
    const int lr = tid >> 5;
    const int c4 = (tid & 31) << 2;
#pragma unroll
    for (int r = lr; r < 32; r += 8){
        *reinterpret_cast<float4*>(&Ks[r][c4]) =
            *reinterpret_cast<const float4*>(&K[cbase + r*NN + nb + c4]);
        *reinterpret_cast<float4*>(&Vs[r][c4]) =
            *reinterpret_cast<const float4*>(&V[cbase + r*NN + nb + c4]);
    }
    __syncthreads();
    const int e0 = tid >> 4;
    const int d0 = tid & 15;
    float m00=0.f, m01=0.f, m10=0.f, m11=0.f;
#pragma unroll
    for (int n = 0; n < 128; n += 4){
        float4 ka = *reinterpret_cast<const float4*>(&Ks[e0][n]);
        float4 kb = *reinterpret_cast<const float4*>(&Ks[e0+16][n]);
        float4 va = *reinterpret_cast<const float4*>(&Vs[d0][n]);
        float4 vb = *reinterpret_cast<const float4*>(&Vs[d0+16][n]);
        m00 += ka.x*va.x + ka.y*va.y + ka.z*va.z + ka.w*va.w;
        m01 += ka.x*vb.x + ka.y*vb.y + ka.z*vb.z + ka.w*vb.w;
        m10 += kb.x*va.x + kb.y*va.y + kb.z*va.z + kb.w*va.w;
        m11 += kb.x*vb.x + kb.y*vb.y + kb.z*vb.z + kb.w*vb.w;
    }
    float* M = g_M + hh*DD*DD;
    atomicAdd(&M[e0*DD + d0],           m00);
    atomicAdd(&M[e0*DD + d0 + 16],      m01);
    atomicAdd(&M[(e0+16)*DD + d0],      m10);
    atomicAdd(&M[(e0+16)*DD + d0 + 16], m11);
}

// ---------------------------------------------------------------------------
// Attention phase 2: O[d,n] = spike(0.1 * sum_e Q[e,n] M[e,d]).
// ---------------------------------------------------------------------------
__global__ void __launch_bounds__(256) qm_kernel()
{
    const float* Q = g_qkv;
    const int hh = blockIdx.x >> 3;
    const int nb = (blockIdx.x & 7) << 7;
    const int cbase = hh * (DD*NN);
    __shared__ float Qs[32][132];
    __shared__ float Ms[32][32];
    const int tid = threadIdx.x;
    const int lr = tid >> 5;
    const int c4 = (tid & 31) << 2;
    if (tid < 256){
        float4 mv = reinterpret_cast<const float4*>(g_M + hh*DD*DD)[tid];
        *reinterpret_cast<float4*>(&Ms[tid >> 3][(tid & 7) << 2]) = mv;
    }
#pragma unroll
    for (int r = lr; r < 32; r += 8){
        *reinterpret_cast<float4*>(&Qs[r][c4]) =
            *reinterpret_cast<const float4*>(&Q[cbase + r*NN + nb + c4]);
    }
    __syncthreads();
    const int dd = tid >> 4;
    const int n0 = (tid & 15) << 2;
    float4 o00 = make_float4(0,0,0,0), o01 = make_float4(0,0,0,0);
    float4 o10 = make_float4(0,0,0,0), o11 = make_float4(0,0,0,0);
#pragma unroll
    for (int e = 0; e < 32; e++){
        float w0 = Ms[e][dd];
        float w1 = Ms[e][dd+16];
        float4 qa = *reinterpret_cast<const float4*>(&Qs[e][n0]);
        float4 qb = *reinterpret_cast<const float4*>(&Qs[e][n0+64]);
        o00.x += w0*qa.x; o00.y += w0*qa.y; o00.z += w0*qa.z; o00.w += w0*qa.w;
        o01.x += w0*qb.x; o01.y += w0*qb.y; o01.z += w0*qb.z; o01.w += w0*qb.w;
        o10.x += w1*qa.x; o10.y += w1*qa.y; o10.z += w1*qa.z; o10.w += w1*qa.w;
        o11.x += w1*qb.x; o11.y += w1*qb.y; o11.z += w1*qb.z; o11.w += w1*qb.w;
    }
    float4 s;
    s = make_float4(spikef(0.1f*o00.x), spikef(0.1f*o00.y), spikef(0.1f*o00.z), spikef(0.1f*o00.w));
    *reinterpret_cast<float4*>(&g_os[cbase + dd*NN + nb + n0]) = s;
    s = make_float4(spikef(0.1f*o01.x), spikef(0.1f*o01.y), spikef(0.1f*o01.z), spikef(0.1f*o01.w));
    *reinterpret_cast<float4*>(&g_os[cbase + dd*NN + nb + n0 + 64]) = s;
    s = make_float4(spikef(0.1f*o10.x), spikef(0.1f*o10.y), spikef(0.1f*o10.z), spikef(0.1f*o10.w));
    *reinterpret_cast<float4*>(&g_os[cbase + (dd+16)*NN + nb + n0]) = s;
    s = make_float4(spikef(0.1f*o11.x), spikef(0.1f*o11.y), spikef(0.1f*o11.z), spikef(0.1f*o11.w));
    *reinterpret_cast<float4*>(&g_os[cbase + (dd+16)*NN + nb + n0 + 64]) = s;
}

// ---------------------------------------------------------------------------
extern "C" void kernel_launch(void* const* d_in, const int* in_sizes, int n_in,
                              void* d_out, int out_size)
{
    const float* q    = (const float*)d_in[0];
    // d_in[1] (key) and d_in[2] (value) are unused by the reference
    const float* qp   = (const float*)d_in[3];
    const float* w    = (const float*)d_in[4];
    const float* b    = (const float*)d_in[5];
    const float* gam  = (const float*)d_in[6];
    const float* bet  = (const float*)d_in[7];
    const float* mean = (const float*)d_in[8];
    const float* var  = (const float*)d_in[9];
    float* out = (float*)d_out;

    cudaFuncSetAttribute(mma_gemm_kernel<0>,
                         cudaFuncAttributeMaxDynamicSharedMemorySize, GEMM_SMEM);
    cudaFuncSetAttribute(mma_gemm_kernel<1>,
                         cudaFuncAttributeMaxDynamicSharedMemorySize, GEMM_SMEM);

    fold_weights_kernel<<<(4*CC*CC)/256, 256>>>(w, b, gam, bet, mean, var);
    prep_kernel<<<(TBCN/4)/256, 256>>>((const float4*)q, (const float4*)qp);

    dim3 gq(NN/128, 768/128, TB);   // 8 x 6 x 8 = 384 CTAs
    mma_gemm_kernel<0><<<gq, 256, GEMM_SMEM>>>(nullptr);

    kv_kernel<<<512, 256>>>();
    qm_kernel<<<512, 256>>>();

    dim3 gp(NN/128, CC/128, TB);    // 8 x 2 x 8 = 128 CTAs
    mma_gemm_kernel<1><<<gp, 256, GEMM_SMEM>>>(out);
}

// round 8
// speedup vs baseline: 2.6290x; 1.0299x over previous
#include <cuda_runtime.h>
#include <cuda_fp16.h>
#include <math.h>
#include <cstdint>

#define TT 4
#define BB 2
#define TB 8
#define NN 1024
#define CC 256
#define HH 8
#define DD 32
#define CN (CC*NN)        // 262144
#define TBCN (TB*CN)      // 2097152

// ---------------------------------------------------------------------------
// Scratch (static device globals: no allocations allowed)
// ---------------------------------------------------------------------------
__device__ float g_tmp[TBCN];                        // query + query_pos (fp32, residual)
__device__ __align__(16) __half g_x16[TBCN];         // spike(tmp) fp16 (qkv GEMM input)
__device__ __align__(16) __half g_qkv[3*TBCN];       // spiked q,k,v fp16 (TB,C,N)
__device__ __align__(16) __half g_os[TBCN];          // spiked attention output fp16
__device__ float g_M[64*DD*DD];                      // per-(tb,h) K^T V (32x32) fp32
__device__ __align__(16) __half g_w16h[4*CC*CC];     // BN-folded weights hi
__device__ __align__(16) __half g_w16l[4*CC*CC];     // BN-folded weights lo
__device__ float g_bp[4*CC];                         // BN-folded biases

// MultiSpike_norm4: round(clamp(x,0,4))/4 ; jnp.round = round-half-even = rintf
__device__ __forceinline__ float spikef(float v){
    v = fminf(fmaxf(v, 0.0f), 4.0f);
    return rintf(v) * 0.25f;
}

__device__ __forceinline__ uint32_t pack2(float a, float b){
    __half2 h = __halves2half2(__float2half_rn(a), __float2half_rn(b));
    return *reinterpret_cast<uint32_t*>(&h);
}

__device__ __forceinline__ uint32_t smem_to_u32(const void* p) {
    uint32_t a;
    asm("{ .reg .u64 t; cvta.to.shared.u64 t, %1; cvt.u32.u64 %0, t; }"
        : "=r"(a) : "l"(p));
    return a;
}

// ---------------------------------------------------------------------------
// Warp MMA primitives (baseline PTX, works on .target sm_100)
// ---------------------------------------------------------------------------
__device__ __forceinline__ void ldsm_x4(uint32_t* a, uint32_t addr){
    asm volatile("ldmatrix.sync.aligned.m8n8.x4.shared.b16 {%0,%1,%2,%3}, [%4];"
        : "=r"(a[0]),"=r"(a[1]),"=r"(a[2]),"=r"(a[3]) : "r"(addr));
}
__device__ __forceinline__ void ldsm_x2_trans(uint32_t* b, uint32_t addr){
    asm volatile("ldmatrix.sync.aligned.m8n8.x2.trans.shared.b16 {%0,%1}, [%2];"
        : "=r"(b[0]),"=r"(b[1]) : "r"(addr));
}
__device__ __forceinline__ void mma16816(float* d, const uint32_t* a, const uint32_t* b){
    asm volatile("mma.sync.aligned.m16n8k16.row.col.f32.f16.f16.f32 "
        "{%0,%1,%2,%3}, {%4,%5,%6,%7}, {%8,%9}, {%0,%1,%2,%3};"
        : "+f"(d[0]),"+f"(d[1]),"+f"(d[2]),"+f"(d[3])
        : "r"(a[0]),"r"(a[1]),"r"(a[2]),"r"(a[3]), "r"(b[0]),"r"(b[1]));
}

// ---------------------------------------------------------------------------
// Fold BN into conv weights, split into fp16 hi/lo planes; fold bias.
// ---------------------------------------------------------------------------
__global__ void fold_weights_kernel(const float* __restrict__ w,
                                    const float* __restrict__ b,
                                    const float* __restrict__ gam,
                                    const float* __restrict__ beta,
                                    const float* __restrict__ mean,
                                    const float* __restrict__ var)
{
    int idx = blockIdx.x * blockDim.x + threadIdx.x;   // 4*C*C threads
    int oc = idx >> 8;                                 // i*C + o
    float inv = gam[oc] * rsqrtf(var[oc] + 1e-5f);
    float wp = w[idx] * inv;
    __half hi = __float2half_rn(wp);
    __half lo = __float2half_rn(wp - __half2float(hi));
    g_w16h[idx] = hi;
    g_w16l[idx] = lo;
    if (idx < 4*CC){
        float invb = gam[idx] * rsqrtf(var[idx] + 1e-5f);
        g_bp[idx] = (b[idx] - mean[idx]) * invb + beta[idx];
    }
}

// ---------------------------------------------------------------------------
// tmp = query + query_pos (fp32) ; x16 = spike(tmp) fp16. Zero g_M.
// ---------------------------------------------------------------------------
__global__ void prep_kernel(const float4* __restrict__ q, const float4* __restrict__ qp)
{
    int i = blockIdx.x * blockDim.x + threadIdx.x;     // TBCN/4 threads
    float4 a = q[i], c = qp[i];
    float4 s = make_float4(a.x + c.x, a.y + c.y, a.z + c.z, a.w + c.w);
    reinterpret_cast<float4*>(g_tmp)[i] = s;
    uint2 hv = make_uint2(pack2(spikef(s.x), spikef(s.y)),
                          pack2(spikef(s.z), spikef(s.w)));
    reinterpret_cast<uint2*>(g_x16)[i] = hv;
    if (i < (64*DD*DD)/4)
        reinterpret_cast<float4*>(g_M)[i] = make_float4(0.f,0.f,0.f,0.f);
}

// ---------------------------------------------------------------------------
// HMMA GEMM. Per CTA: D[m=128, n=128] = sum_k (Whi+Wlo)[m,k] * X[k,n].
// A = weights fp16 row-major [m,k] (2 planes). B = fp16 activations [k,n].
// 8 warps: 2 (m) x 4 (n); warp tile 64x32; K-chunk 64.
// MODE 0: qkv (src g_x16, M=768, out g_qkv fp16 split by branch, spike)
// MODE 1: proj (src g_os,  M=256, out fp32 = D + bias + residual g_tmp)
// ---------------------------------------------------------------------------
#define AS_STRIDE 72                     // halves per A row (144B: 16-aligned, %128=16)
#define BS_STRIDE 136                    // halves per B row (272B)
#define AS_BYTES (2*128*AS_STRIDE*2)     // 36864
#define BS_BYTES (64*BS_STRIDE*2)        // 17408
#define GEMM_SMEM (AS_BYTES + BS_BYTES)  // 54272

template<int MODE>
__global__ void __launch_bounds__(256, 2) mma_gemm_kernel(float* __restrict__ out)
{
    extern __shared__ __half smem[];
    __half* As = smem;                          // [2][128][AS_STRIDE]
    __half* Bs = smem + 2*128*AS_STRIDE;        // [64][BS_STRIDE]
    const int tid  = threadIdx.x;
    const int wid  = tid >> 5;
    const int lane = tid & 31;
    const int tb = blockIdx.z;
    const int bn = blockIdx.x * 128;
    const int bm = blockIdx.y * 128;
    const int WOFF = (MODE == 0) ? 0 : 768;
    const int wm = (wid & 1) * 64;              // warp m offset
    const int wn = (wid >> 1) * 32;             // warp n offset

    float acc[16][4];
#pragma unroll
    for (int i = 0; i < 16; i++)
#pragma unroll
        for (int j = 0; j < 4; j++) acc[i][j] = 0.f;

    const __half* xsrc = (MODE == 0 ? g_x16 : g_os) + tb*CN + bn;

    for (int k0 = 0; k0 < CC; k0 += 64){
        // ---- stage A (both planes), 128 rows x 64 k-halves each ----
#pragma unroll
        for (int p = 0; p < 2; p++){
            const __half* src = (p ? g_w16l : g_w16h) + (WOFF + bm)*CC + k0;
#pragma unroll
            for (int j = 0; j < 4; j++){
                int idx = tid + 256*j;          // 0..1023
                int r = idx >> 3;               // m row
                int c8 = (idx & 7) << 3;        // k offset (8 halves)
                uint4 v = *reinterpret_cast<const uint4*>(src + r*CC + c8);
                *reinterpret_cast<uint4*>(&As[(p*128 + r)*AS_STRIDE + c8]) = v;
            }
        }
        // ---- stage B: 64 k rows x 128 n halves, direct fp16 copy ----
#pragma unroll
        for (int j = 0; j < 4; j++){
            int idx = tid + 256*j;              // 0..1023
            int r = idx >> 4;                   // k row 0..63
            int c8 = (idx & 15) << 3;           // n offset (8 halves)
            uint4 v = *reinterpret_cast<const uint4*>(xsrc + (k0 + r)*NN + c8);
            *reinterpret_cast<uint4*>(&Bs[r*BS_STRIDE + c8]) = v;
        }
        __syncthreads();

        // ---- compute: 4 k16 steps ----
#pragma unroll
        for (int kk = 0; kk < 64; kk += 16){
            uint32_t bf[4][2];
#pragma unroll
            for (int nt = 0; nt < 4; nt++){
                uint32_t addr = smem_to_u32(
                    &Bs[(kk + (lane & 15))*BS_STRIDE + wn + nt*8]);
                ldsm_x2_trans(bf[nt], addr);
            }
#pragma unroll
            for (int mt = 0; mt < 4; mt++){
#pragma unroll
                for (int p = 0; p < 2; p++){
                    uint32_t af[4];
                    uint32_t addr = smem_to_u32(
                        &As[(p*128 + wm + mt*16 + (lane & 15))*AS_STRIDE
                            + kk + (lane >> 4)*8]);
                    ldsm_x4(af, addr);
#pragma unroll
                    for (int nt = 0; nt < 4; nt++)
                        mma16816(acc[mt*4 + nt], af, bf[nt]);
                }
            }
        }
        __syncthreads();
    }

    // ---- epilogue ----
#pragma unroll
    for (int mt = 0; mt < 4; mt++){
#pragma unroll
        for (int nt = 0; nt < 4; nt++){
            const float* a = acc[mt*4 + nt];
            int row = wm + mt*16 + (lane >> 2);      // 0..127 (and +8)
            int col = wn + nt*8 + ((lane & 3) << 1); // 0..126, even
            if (MODE == 0){
                int gm0 = bm + row, gm1 = gm0 + 8;
                float b0 = g_bp[gm0], b1 = g_bp[gm1];
                uint32_t v0 = pack2(spikef(a[0] + b0), spikef(a[1] + b0));
                uint32_t v1 = pack2(spikef(a[2] + b1), spikef(a[3] + b1));
                *reinterpret_cast<uint32_t*>(
                    &g_qkv[(gm0 >> 8)*TBCN + tb*CN + (gm0 & 255)*NN + bn + col]) = v0;
                *reinterpret_cast<uint32_t*>(
                    &g_qkv[(gm1 >> 8)*TBCN + tb*CN + (gm1 & 255)*NN + bn + col]) = v1;
            } else {
                int gm0 = bm + row, gm1 = gm0 + 8;
                float b0 = g_bp[768 + gm0], b1 = g_bp[768 + gm1];
                int i0 = tb*CN + gm0*NN + bn + col;
                int i1 = tb*CN + gm1*NN + bn + col;
                float2 r0 = *reinterpret_cast<const float2*>(&g_tmp[i0]);
                float2 r1 = *reinterpret_cast<const float2*>(&g_tmp[i1]);
                float2 v0 = make_float2(a[0] + b0 + r0.x, a[1] + b0 + r0.y);
                float2 v1 = make_float2(a[2] + b1 + r1.x, a[3] + b1 + r1.y);
                *reinterpret_cast<float2*>(&out[i0]) = v0;
                *reinterpret_cast<float2*>(&out[i1]) = v1;
            }
        }
    }
}

// ---------------------------------------------------------------------------
// Attention phase 1: partial M[e,d] += sum_{n chunk} K[e,n]V[d,n]; fp16 in,
// fp32 accumulate (exact). grid 512 = 64 heads x 8 n-chunks.
// ---------------------------------------------------------------------------
__global__ void __launch_bounds__(256) kv_kernel()
{
    const __half* K = g_qkv + TBCN;
    const __half* V = g_qkv + 2*TBCN;
    const int hh = blockIdx.x >> 3;
    const int nb = (blockIdx.x & 7) << 7;
    const int cbase = hh * (DD*NN);
    __shared__ __half Ks[32][136];
    __shared__ __half Vs[32][136];
    const int tid = threadIdx.x;
    const int lr = tid >> 4;             // 0..15 (16 row-groups)
    const int c8 = (tid & 15) << 3;      // 0..120 (8 halves)
#pragma unroll
    for (int r = lr; r < 32; r += 16){
        *reinterpret_cast<uint4*>(&Ks[r][c8]) =
            *reinterpret_cast<const uint4*>(&K[cbase + r*NN + nb + c8]);
        *reinterpret_cast<uint4*>(&Vs[r][c8]) =
            *reinterpret_cast<const uint4*>(&V[cbase + r*NN + nb + c8]);
    }
    __syncthreads();
    const int e0 = tid >> 4;
    const int d0 = tid & 15;
    float m00=0.f, m01=0.f, m10=0.f, m11=0.f;
#pragma unroll
    for (int n = 0; n < 128; n += 2){
        float2 ka = __half22float2(*reinterpret_cast<const __half2*>(&Ks[e0][n]));
        float2 kb = __half22float2(*reinterpret_cast<const __half2*>(&Ks[e0+16][n]));
        float2 va = __half22float2(*reinterpret_cast<const __half2*>(&Vs[d0][n]));
        float2 vb = __half22float2(*reinterpret_cast<const __half2*>(&Vs[d0+16][n]));
        m00 += ka.x*va.x + ka.y*va.y;
        m01 += ka.x*vb.x + ka.y*vb.y;
        m10 += kb.x*va.x + kb.y*va.y;
        m11 += kb.x*vb.x + kb.y*vb.y;
    }
    float* M = g_M + hh*DD*DD;
    atomicAdd(&M[e0*DD + d0],           m00);
    atomicAdd(&M[e0*DD + d0 + 16],      m01);
    atomicAdd(&M[(e0+16)*DD + d0],      m10);
    atomicAdd(&M[(e0+16)*DD + d0 + 16], m11);
}

// ---------------------------------------------------------------------------
// Attention phase 2: O[d,n] = spike(0.1 * sum_e Q[e,n] M[e,d]); Q fp16,
// M fp32, fp32 accumulate, out fp16.
// ---------------------------------------------------------------------------
__global__ void __launch_bounds__(256) qm_kernel()
{
    const __half* Q = g_qkv;
    const int hh = blockIdx.x >> 3;
    const int nb = (blockIdx.x & 7) << 7;
    const int cbase = hh * (DD*NN);
    __shared__ __half Qs[32][136];
    __shared__ float Ms[32][32];
    const int tid = threadIdx.x;
    const int lr = tid >> 4;
    const int c8 = (tid & 15) << 3;
    if (tid < 256){
        float4 mv = reinterpret_cast<const float4*>(g_M + hh*DD*DD)[tid];
        *reinterpret_cast<float4*>(&Ms[tid >> 3][(tid & 7) << 2]) = mv;
    }
#pragma unroll
    for (int r = lr; r < 32; r += 16){
        *reinterpret_cast<uint4*>(&Qs[r][c8]) =
            *reinterpret_cast<const uint4*>(&Q[cbase + r*NN + nb + c8]);
    }
    __syncthreads();
    const int dd = tid >> 4;             // row pair (dd, dd+16)
    const int n0 = (tid & 15) << 2;      // col groups n0 and n0+64 (4 halves each)
    float4 o00 = make_float4(0,0,0,0), o01 = make_float4(0,0,0,0);
    float4 o10 = make_float4(0,0,0,0), o11 = make_float4(0,0,0,0);
#pragma unroll
    for (int e = 0; e < 32; e++){
        float w0 = Ms[e][dd];
        float w1 = Ms[e][dd+16];
        float2 qa0 = __half22float2(*reinterpret_cast<const __half2*>(&Qs[e][n0]));
        float2 qa1 = __half22float2(*reinterpret_cast<const __half2*>(&Qs[e][n0+2]));
        float2 qb0 = __half22float2(*reinterpret_cast<const __half2*>(&Qs[e][n0+64]));
        float2 qb1 = __half22float2(*reinterpret_cast<const __half2*>(&Qs[e][n0+66]));
        o00.x += w0*qa0.x; o00.y += w0*qa0.y; o00.z += w0*qa1.x; o00.w += w0*qa1.y;
        o01.x += w0*qb0.x; o01.y += w0*qb0.y; o01.z += w0*qb1.x; o01.w += w0*qb1.y;
        o10.x += w1*qa0.x; o10.y += w1*qa0.y; o10.z += w1*qa1.x; o10.w += w1*qa1.y;
        o11.x += w1*qb0.x; o11.y += w1*qb0.y; o11.z += w1*qb1.x; o11.w += w1*qb1.y;
    }
    uint2 s;
    s = make_uint2(pack2(spikef(0.1f*o00.x), spikef(0.1f*o00.y)),
                   pack2(spikef(0.1f*o00.z), spikef(0.1f*o00.w)));
    *reinterpret_cast<uint2*>(&g_os[cbase + dd*NN + nb + n0]) = s;
    s = make_uint2(pack2(spikef(0.1f*o01.x), spikef(0.1f*o01.y)),
                   pack2(spikef(0.1f*o01.z), spikef(0.1f*o01.w)));
    *reinterpret_cast<uint2*>(&g_os[cbase + dd*NN + nb + n0 + 64]) = s;
    s = make_uint2(pack2(spikef(0.1f*o10.x), spikef(0.1f*o10.y)),
                   pack2(spikef(0.1f*o10.z), spikef(0.1f*o10.w)));
    *reinterpret_cast<uint2*>(&g_os[cbase + (dd+16)*NN + nb + n0]) = s;
    s = make_uint2(pack2(spikef(0.1f*o11.x), spikef(0.1f*o11.y)),
                   pack2(spikef(0.1f*o11.z), spikef(0.1f*o11.w)));
    *reinterpret_cast<uint2*>(&g_os[cbase + (dd+16)*NN + nb + n0 + 64]) = s;
}

// ---------------------------------------------------------------------------
extern "C" void kernel_launch(void* const* d_in, const int* in_sizes, int n_in,
                              void* d_out, int out_size)
{
    const float* q    = (const float*)d_in[0];
    // d_in[1] (key) and d_in[2] (value) are unused by the reference
    const float* qp   = (const float*)d_in[3];
    const float* w    = (const float*)d_in[4];
    const float* b    = (const float*)d_in[5];
    const float* gam  = (const float*)d_in[6];
    const float* bet  = (const float*)d_in[7];
    const float* mean = (const float*)d_in[8];
    const float* var  = (const float*)d_in[9];
    float* out = (float*)d_out;

    cudaFuncSetAttribute(mma_gemm_kernel<0>,
                         cudaFuncAttributeMaxDynamicSharedMemorySize, GEMM_SMEM);
    cudaFuncSetAttribute(mma_gemm_kernel<1>,
                         cudaFuncAttributeMaxDynamicSharedMemorySize, GEMM_SMEM);

    fold_weights_kernel<<<(4*CC*CC)/256, 256>>>(w, b, gam, bet, mean, var);
    prep_kernel<<<(TBCN/4)/256, 256>>>((const float4*)q, (const float4*)qp);

    dim3 gq(NN/128, 768/128, TB);   // 8 x 6 x 8 = 384 CTAs
    mma_gemm_kernel<0><<<gq, 256, GEMM_SMEM>>>(nullptr);

    kv_kernel<<<512, 256>>>();
    qm_kernel<<<512, 256>>>();

    dim3 gp(NN/128, CC/128, TB);    // 8 x 2 x 8 = 128 CTAs
    mma_gemm_kernel<1><<<gp, 256, GEMM_SMEM>>>(out);
}

// round 10
// speedup vs baseline: 2.8727x; 1.0927x over previous
#include <cuda_runtime.h>
#include <cuda_fp16.h>
#include <math.h>
#include <cstdint>

#define TT 4
#define BB 2
#define TB 8
#define NN 1024
#define CC 256
#define HH 8
#define DD 32
#define CN (CC*NN)        // 262144
#define TBCN (TB*CN)      // 2097152

// ---------------------------------------------------------------------------
// Scratch (static device globals: no allocations allowed)
// ---------------------------------------------------------------------------
__device__ float g_tmp[TBCN];                        // query + query_pos (fp32, residual)
__device__ __align__(16) __half g_x16[TBCN];         // spike(tmp) fp16 (qkv GEMM input)
__device__ __align__(16) __half g_qkv[3*TBCN];       // spiked q,k,v fp16 (TB,C,N)
__device__ __align__(16) __half g_os[TBCN];          // spiked attention output fp16
__device__ __align__(16) __half g_Mh[64*DD*DD];      // K^T V hi, [head][d][e] fp16
__device__ __align__(16) __half g_Ml[64*DD*DD];      // K^T V lo, [head][d][e] fp16
__device__ __align__(16) __half g_w16h[4*CC*CC];     // BN-folded weights hi
__device__ __align__(16) __half g_w16l[4*CC*CC];     // BN-folded weights lo
__device__ float g_bp[4*CC];                         // BN-folded biases

// MultiSpike_norm4: round(clamp(x,0,4))/4 ; jnp.round = round-half-even = rintf
__device__ __forceinline__ float spikef(float v){
    v = fminf(fmaxf(v, 0.0f), 4.0f);
    return rintf(v) * 0.25f;
}

__device__ __forceinline__ uint32_t pack2(float a, float b){
    __half2 h = __halves2half2(__float2half_rn(a), __float2half_rn(b));
    return *reinterpret_cast<uint32_t*>(&h);
}

__device__ __forceinline__ uint32_t smem_to_u32(const void* p) {
    uint32_t a;
    asm("{ .reg .u64 t; cvta.to.shared.u64 t, %1; cvt.u32.u64 %0, t; }"
        : "=r"(a) : "l"(p));
    return a;
}

// ---------------------------------------------------------------------------
// Warp MMA primitives (baseline PTX, works on .target sm_100)
// ---------------------------------------------------------------------------
__device__ __forceinline__ void ldsm_x4(uint32_t* a, uint32_t addr){
    asm volatile("ldmatrix.sync.aligned.m8n8.x4.shared.b16 {%0,%1,%2,%3}, [%4];"
        : "=r"(a[0]),"=r"(a[1]),"=r"(a[2]),"=r"(a[3]) : "r"(addr));
}
__device__ __forceinline__ void ldsm_x2(uint32_t* b, uint32_t addr){
    asm volatile("ldmatrix.sync.aligned.m8n8.x2.shared.b16 {%0,%1}, [%2];"
        : "=r"(b[0]),"=r"(b[1]) : "r"(addr));
}
__device__ __forceinline__ void ldsm_x2_trans(uint32_t* b, uint32_t addr){
    asm volatile("ldmatrix.sync.aligned.m8n8.x2.trans.shared.b16 {%0,%1}, [%2];"
        : "=r"(b[0]),"=r"(b[1]) : "r"(addr));
}
__device__ __forceinline__ void mma16816(float* d, const uint32_t* a, const uint32_t* b){
    asm volatile("mma.sync.aligned.m16n8k16.row.col.f32.f16.f16.f32 "
        "{%0,%1,%2,%3}, {%4,%5,%6,%7}, {%8,%9}, {%0,%1,%2,%3};"
        : "+f"(d[0]),"+f"(d[1]),"+f"(d[2]),"+f"(d[3])
        : "r"(a[0]),"r"(a[1]),"r"(a[2]),"r"(a[3]), "r"(b[0]),"r"(b[1]));
}

// ---------------------------------------------------------------------------
// Fold BN into conv weights, split into fp16 hi/lo planes; fold bias.
// ---------------------------------------------------------------------------
__global__ void fold_weights_kernel(const float* __restrict__ w,
                                    const float* __restrict__ b,
                                    const float* __restrict__ gam,
                                    const float* __restrict__ beta,
                                    const float* __restrict__ mean,
                                    const float* __restrict__ var)
{
    int idx = blockIdx.x * blockDim.x + threadIdx.x;   // 4*C*C threads
    int oc = idx >> 8;                                 // i*C + o
    float inv = gam[oc] * rsqrtf(var[oc] + 1e-5f);
    float wp = w[idx] * inv;
    __half hi = __float2half_rn(wp);
    __half lo = __float2half_rn(wp - __half2float(hi));
    g_w16h[idx] = hi;
    g_w16l[idx] = lo;
    if (idx < 4*CC){
        float invb = gam[idx] * rsqrtf(var[idx] + 1e-5f);
        g_bp[idx] = (b[idx] - mean[idx]) * invb + beta[idx];
    }
}

// ---------------------------------------------------------------------------
// tmp = query + query_pos (fp32) ; x16 = spike(tmp) fp16.
// ---------------------------------------------------------------------------
__global__ void prep_kernel(const float4* __restrict__ q, const float4* __restrict__ qp)
{
    int i = blockIdx.x * blockDim.x + threadIdx.x;     // TBCN/4 threads
    float4 a = q[i], c = qp[i];
    float4 s = make_float4(a.x + c.x, a.y + c.y, a.z + c.z, a.w + c.w);
    reinterpret_cast<float4*>(g_tmp)[i] = s;
    uint2 hv = make_uint2(pack2(spikef(s.x), spikef(s.y)),
                          pack2(spikef(s.z), spikef(s.w)));
    reinterpret_cast<uint2*>(g_x16)[i] = hv;
}

// ---------------------------------------------------------------------------
// HMMA GEMM. Per CTA: D[m=128, n=128] = sum_k (Whi+Wlo)[m,k] * X[k,n].
// MODE 0: qkv (src g_x16, M=768, out g_qkv fp16 split by branch, spike)
// MODE 1: proj (src g_os,  M=256, out fp32 = D + bias + residual g_tmp)
// ---------------------------------------------------------------------------
#define AS_STRIDE 72                     // halves per A row (144B: 16-aligned, %128=16)
#define BS_STRIDE 136                    // halves per B row (272B)
#define AS_BYTES (2*128*AS_STRIDE*2)     // 36864
#define BS_BYTES (64*BS_STRIDE*2)        // 17408
#define GEMM_SMEM (AS_BYTES + BS_BYTES)  // 54272

template<int MODE>
__global__ void __launch_bounds__(256, 2) mma_gemm_kernel(float* __restrict__ out)
{
    extern __shared__ __half smem[];
    __half* As = smem;                          // [2][128][AS_STRIDE]
    __half* Bs = smem + 2*128*AS_STRIDE;        // [64][BS_STRIDE]
    const int tid  = threadIdx.x;
    const int wid  = tid >> 5;
    const int lane = tid & 31;
    const int tb = blockIdx.z;
    const int bn = blockIdx.x * 128;
    const int bm = blockIdx.y * 128;
    const int WOFF = (MODE == 0) ? 0 : 768;
    const int wm = (wid & 1) * 64;              // warp m offset
    const int wn = (wid >> 1) * 32;             // warp n offset

    float acc[16][4];
#pragma unroll
    for (int i = 0; i < 16; i++)
#pragma unroll
        for (int j = 0; j < 4; j++) acc[i][j] = 0.f;

    const __half* xsrc = (MODE == 0 ? g_x16 : g_os) + tb*CN + bn;

    for (int k0 = 0; k0 < CC; k0 += 64){
        // ---- stage A (both planes), 128 rows x 64 k-halves each ----
#pragma unroll
        for (int p = 0; p < 2; p++){
            const __half* src = (p ? g_w16l : g_w16h) + (WOFF + bm)*CC + k0;
#pragma unroll
            for (int j = 0; j < 4; j++){
                int idx = tid + 256*j;          // 0..1023
                int r = idx >> 3;               // m row
                int c8 = (idx & 7) << 3;        // k offset (8 halves)
                uint4 v = *reinterpret_cast<const uint4*>(src + r*CC + c8);
                *reinterpret_cast<uint4*>(&As[(p*128 + r)*AS_STRIDE + c8]) = v;
            }
        }
        // ---- stage B: 64 k rows x 128 n halves, direct fp16 copy ----
#pragma unroll
        for (int j = 0; j < 4; j++){
            int idx = tid + 256*j;              // 0..1023
            int r = idx >> 4;                   // k row 0..63
            int c8 = (idx & 15) << 3;           // n offset (8 halves)
            uint4 v = *reinterpret_cast<const uint4*>(xsrc + (k0 + r)*NN + c8);
            *reinterpret_cast<uint4*>(&Bs[r*BS_STRIDE + c8]) = v;
        }
        __syncthreads();

        // ---- compute: 4 k16 steps ----
#pragma unroll
        for (int kk = 0; kk < 64; kk += 16){
            uint32_t bf[4][2];
#pragma unroll
            for (int nt = 0; nt < 4; nt++){
                uint32_t addr = smem_to_u32(
                    &Bs[(kk + (lane & 15))*BS_STRIDE + wn + nt*8]);
                ldsm_x2_trans(bf[nt], addr);
            }
#pragma unroll
            for (int mt = 0; mt < 4; mt++){
#pragma unroll
                for (int p = 0; p < 2; p++){
                    uint32_t af[4];
                    uint32_t addr = smem_to_u32(
                        &As[(p*128 + wm + mt*16 + (lane & 15))*AS_STRIDE
                            + kk + (lane >> 4)*8]);
                    ldsm_x4(af, addr);
#pragma unroll
                    for (int nt = 0; nt < 4; nt++)
                        mma16816(acc[mt*4 + nt], af, bf[nt]);
                }
            }
        }
        __syncthreads();
    }

    // ---- epilogue ----
#pragma unroll
    for (int mt = 0; mt < 4; mt++){
#pragma unroll
        for (int nt = 0; nt < 4; nt++){
            const float* a = acc[mt*4 + nt];
            int row = wm + mt*16 + (lane >> 2);      // 0..127 (and +8)
            int col = wn + nt*8 + ((lane & 3) << 1); // 0..126, even
            if (MODE == 0){
                int gm0 = bm + row, gm1 = gm0 + 8;
                float b0 = g_bp[gm0], b1 = g_bp[gm1];
                uint32_t v0 = pack2(spikef(a[0] + b0), spikef(a[1] + b0));
                uint32_t v1 = pack2(spikef(a[2] + b1), spikef(a[3] + b1));
                *reinterpret_cast<uint32_t*>(
                    &g_qkv[(gm0 >> 8)*TBCN + tb*CN + (gm0 & 255)*NN + bn + col]) = v0;
                *reinterpret_cast<uint32_t*>(
                    &g_qkv[(gm1 >> 8)*TBCN + tb*CN + (gm1 & 255)*NN + bn + col]) = v1;
            } else {
                int gm0 = bm + row, gm1 = gm0 + 8;
                float b0 = g_bp[768 + gm0], b1 = g_bp[768 + gm1];
                int i0 = tb*CN + gm0*NN + bn + col;
                int i1 = tb*CN + gm1*NN + bn + col;
                float2 r0 = *reinterpret_cast<const float2*>(&g_tmp[i0]);
                float2 r1 = *reinterpret_cast<const float2*>(&g_tmp[i1]);
                float2 v0 = make_float2(a[0] + b0 + r0.x, a[1] + b0 + r0.y);
                float2 v1 = make_float2(a[2] + b1 + r1.x, a[3] + b1 + r1.y);
                *reinterpret_cast<float2*>(&out[i0]) = v0;
                *reinterpret_cast<float2*>(&out[i1]) = v1;
            }
        }
    }
}

// ---------------------------------------------------------------------------
// Attention phase 1 (HMMA): per head, M[e,d] = sum_n K[e,n]*V[d,n].
// A = K tile [e][n] row-major (m=e, k=n). B = V tile [d][n] (= B^T layout,
// ldsm non-trans). 64 CTAs (1/head), 8 warps each own a 16-wide k-slice per
// 128-n chunk; warp partials reduced via smem (aliases the K/V tile buffer).
// Output: M split exactly into fp16 hi+lo (M has <=21 significant bits),
// stored TRANSPOSED [d][e] for the qm kernel.
// ---------------------------------------------------------------------------
#define KV_STRIDE 136
__global__ void __launch_bounds__(256) kv_kernel()
{
    __shared__ __align__(16) char sbuf[32768];
    __half (*Ks)[KV_STRIDE] = reinterpret_cast<__half(*)[KV_STRIDE]>(sbuf);
    __half (*Vs)[KV_STRIDE] = reinterpret_cast<__half(*)[KV_STRIDE]>(sbuf + 32*KV_STRIDE*2);
    float (*red)[1024] = reinterpret_cast<float(*)[1024]>(sbuf);   // aliases Ks/Vs

    const int hh = blockIdx.x;                   // 0..63
    const int tid = threadIdx.x;
    const int wid = tid >> 5;
    const int lane = tid & 31;
    const __half* K = g_qkv + TBCN   + hh*DD*NN;
    const __half* V = g_qkv + 2*TBCN + hh*DD*NN;

    float acc[2][4][4];
#pragma unroll
    for (int mt = 0; mt < 2; mt++)
#pragma unroll
        for (int nt = 0; nt < 4; nt++)
#pragma unroll
            for (int i = 0; i < 4; i++) acc[mt][nt][i] = 0.f;

    const int kslice = wid * 16;
    for (int ch = 0; ch < 8; ch++){
        const int nb = ch << 7;
#pragma unroll
        for (int j = 0; j < 2; j++){
            int idx = tid + 256*j;               // 0..511
            int r = idx >> 4;                    // row 0..31
            int c8 = (idx & 15) << 3;            // 0..120
            *reinterpret_cast<uint4*>(&Ks[r][c8]) =
                *reinterpret_cast<const uint4*>(&K[r*NN + nb + c8]);
            *reinterpret_cast<uint4*>(&Vs[r][c8]) =
                *reinterpret_cast<const uint4*>(&V[r*NN + nb + c8]);
        }
        __syncthreads();
        uint32_t a0[4], a1[4];
        ldsm_x4(a0, smem_to_u32(&Ks[lane & 15][kslice + (lane >> 4)*8]));
        ldsm_x4(a1, smem_to_u32(&Ks[16 + (lane & 15)][kslice + (lane >> 4)*8]));
#pragma unroll
        for (int nt = 0; nt < 4; nt++){
            uint32_t bf[2];
            ldsm_x2(bf, smem_to_u32(&Vs[nt*8 + (lane & 7)][kslice + ((lane >> 3) & 1)*8]));
            mma16816(acc[0][nt], a0, bf);
            mma16816(acc[1][nt], a1, bf);
        }
        __syncthreads();
    }

    // ---- cross-warp reduction (red aliases Ks/Vs; last sync above protects) ----
#pragma unroll
    for (int mt = 0; mt < 2; mt++)
#pragma unroll
        for (int nt = 0; nt < 4; nt++)
#pragma unroll
            for (int i = 0; i < 4; i++){
                int e = mt*16 + (lane >> 2) + ((i >= 2) ? 8 : 0);
                int d = nt*8 + ((lane & 3) << 1) + (i & 1);
                red[wid][e*32 + d] = acc[mt][nt][i];
            }
    __syncthreads();
#pragma unroll
    for (int i = 0; i < 4; i++){
        int j = tid*4 + i;                       // 0..1023 ; j = e*32+d
        float s = red[0][j] + red[1][j] + red[2][j] + red[3][j]
                + red[4][j] + red[5][j] + red[6][j] + red[7][j];
        __half hi = __float2half_rn(s);
        __half lo = __float2half_rn(s - __half2float(hi));
        int e = j >> 5, d = j & 31;
        g_Mh[hh*1024 + d*32 + e] = hi;           // store transposed [d][e]
        g_Ml[hh*1024 + d*32 + e] = lo;
    }
}

// ---------------------------------------------------------------------------
// Attention phase 2 (HMMA): O[d,n] = spike(0.1 * sum_e M[e,d]*Q[e,n]).
// A = M^T [d][e] hi/lo fp16 (exact split). B = Q [e][n] (trans ldsm).
// 128 CTAs = 64 heads x 2 n-halves; 8 warps x 64-n windows.
// ---------------------------------------------------------------------------
#define QS_STRIDE 520
__global__ void __launch_bounds__(256) qm_kernel()
{
    __shared__ __align__(16) __half Qs[32][QS_STRIDE];
    __shared__ __align__(16) __half Mh[32][40];
    __shared__ __align__(16) __half Ml[32][40];
    const int hh = blockIdx.x >> 1;
    const int nb = (blockIdx.x & 1) << 9;        // 0 or 512
    const int tid = threadIdx.x;
    const int wid = tid >> 5;
    const int lane = tid & 31;
    const int cbase = hh * (DD*NN);
    const __half* Q = g_qkv + cbase;

    // load M hi/lo ([d][e] layout already)
#pragma unroll
    for (int i = tid; i < 1024; i += 256){
        Mh[i >> 5][i & 31] = g_Mh[hh*1024 + i];
        Ml[i >> 5][i & 31] = g_Ml[hh*1024 + i];
    }
    // load Q chunk [32 e][512 n]
#pragma unroll
    for (int j = 0; j < 8; j++){
        int idx = tid + 256*j;                   // 0..2047
        int r = idx >> 6;                        // e row 0..31
        int c8 = (idx & 63) << 3;                // 0..504
        *reinterpret_cast<uint4*>(&Qs[r][c8]) =
            *reinterpret_cast<const uint4*>(&Q[r*NN + nb + c8]);
    }
    __syncthreads();

    const int wn = wid * 64;
    float acc[2][8][4];
#pragma unroll
    for (int mt = 0; mt < 2; mt++)
#pragma unroll
        for (int nt = 0; nt < 8; nt++)
#pragma unroll
            for (int i = 0; i < 4; i++) acc[mt][nt][i] = 0.f;

#pragma unroll
    for (int e0 = 0; e0 < 32; e0 += 16){
        uint32_t bf[8][2];
#pragma unroll
        for (int nt = 0; nt < 8; nt++)
            ldsm_x2_trans(bf[nt],
                smem_to_u32(&Qs[e0 + (lane & 15)][wn + nt*8]));
#pragma unroll
        for (int mt = 0; mt < 2; mt++){
            uint32_t ah[4], al[4];
            ldsm_x4(ah, smem_to_u32(&Mh[mt*16 + (lane & 15)][e0 + (lane >> 4)*8]));
            ldsm_x4(al, smem_to_u32(&Ml[mt*16 + (lane & 15)][e0 + (lane >> 4)*8]));
#pragma unroll
            for (int nt = 0; nt < 8; nt++){
                mma16816(acc[mt][nt], ah, bf[nt]);
                mma16816(acc[mt][nt], al, bf[nt]);
            }
        }
    }

    // epilogue: spike(0.1*O) -> g_os fp16
#pragma unroll
    for (int mt = 0; mt < 2; mt++){
#pragma unroll
        for (int nt = 0; nt < 8; nt++){
            const float* a = acc[mt][nt];
            int d0 = mt*16 + (lane >> 2);
            int n  = nb + wn + nt*8 + ((lane & 3) << 1);
            uint32_t v0 = pack2(spikef(0.1f*a[0]), spikef(0.1f*a[1]));
            uint32_t v1 = pack2(spikef(0.1f*a[2]), spikef(0.1f*a[3]));
            *reinterpret_cast<uint32_t*>(&g_os[cbase + d0*NN + n]) = v0;
            *reinterpret_cast<uint32_t*>(&g_os[cbase + (d0+8)*NN + n]) = v1;
        }
    }
}

// ---------------------------------------------------------------------------
extern "C" void kernel_launch(void* const* d_in, const int* in_sizes, int n_in,
                              void* d_out, int out_size)
{
    const float* q    = (const float*)d_in[0];
    // d_in[1] (key) and d_in[2] (value) are unused by the reference
    const float* qp   = (const float*)d_in[3];
    const float* w    = (const float*)d_in[4];
    const float* b    = (const float*)d_in[5];
    const float* gam  = (const float*)d_in[6];
    const float* bet  = (const float*)d_in[7];
    const float* mean = (const float*)d_in[8];
    const float* var  = (const float*)d_in[9];
    float* out = (float*)d_out;

    cudaFuncSetAttribute(mma_gemm_kernel<0>,
                         cudaFuncAttributeMaxDynamicSharedMemorySize, GEMM_SMEM);
    cudaFuncSetAttribute(mma_gemm_kernel<1>,
                         cudaFuncAttributeMaxDynamicSharedMemorySize, GEMM_SMEM);

    fold_weights_kernel<<<(4*CC*CC)/256, 256>>>(w, b, gam, bet, mean, var);
    prep_kernel<<<(TBCN/4)/256, 256>>>((const float4*)q, (const float4*)qp);

    dim3 gq(NN/128, 768/128, TB);   // 8 x 6 x 8 = 384 CTAs
    mma_gemm_kernel<0><<<gq, 256, GEMM_SMEM>>>(nullptr);

    kv_kernel<<<64, 256>>>();
    qm_kernel<<<128, 256>>>();

    dim3 gp(NN/128, CC/128, TB);    // 8 x 2 x 8 = 128 CTAs
    mma_gemm_kernel<1><<<gp, 256, GEMM_SMEM>>>(out);
}

// round 11
// speedup vs baseline: 2.9668x; 1.0327x over previous
#include <cuda_runtime.h>
#include <cuda_fp16.h>
#include <math.h>
#include <cstdint>

#define TT 4
#define BB 2
#define TB 8
#define NN 1024
#define CC 256
#define HH 8
#define DD 32
#define CN (CC*NN)        // 262144
#define TBCN (TB*CN)      // 2097152

// ---------------------------------------------------------------------------
// Scratch (static device globals: no allocations allowed)
// ---------------------------------------------------------------------------
__device__ float g_tmp[TBCN];                        // query + query_pos (fp32, residual)
__device__ __align__(16) __half g_x16[TBCN];         // spike(tmp) fp16 (qkv GEMM input)
__device__ __align__(16) __half g_qkv[3*TBCN];       // spiked q,k,v fp16 (TB,C,N)
__device__ __align__(16) __half g_os[TBCN];          // spiked attention output fp16
__device__ float g_M[64*DD*DD];                      // per-(tb,h) K^T V fp32 [e][d]
__device__ __align__(16) __half g_w16h[4*CC*CC];     // BN-folded weights hi
__device__ __align__(16) __half g_w16l[4*CC*CC];     // BN-folded weights lo
__device__ float g_bp[4*CC];                         // BN-folded biases

// MultiSpike_norm4: round(clamp(x,0,4))/4 ; jnp.round = round-half-even = rintf
__device__ __forceinline__ float spikef(float v){
    v = fminf(fmaxf(v, 0.0f), 4.0f);
    return rintf(v) * 0.25f;
}

__device__ __forceinline__ uint32_t pack2(float a, float b){
    __half2 h = __halves2half2(__float2half_rn(a), __float2half_rn(b));
    return *reinterpret_cast<uint32_t*>(&h);
}

__device__ __forceinline__ uint32_t smem_to_u32(const void* p) {
    uint32_t a;
    asm("{ .reg .u64 t; cvta.to.shared.u64 t, %1; cvt.u32.u64 %0, t; }"
        : "=r"(a) : "l"(p));
    return a;
}

// ---------------------------------------------------------------------------
// Warp MMA primitives (baseline PTX, works on .target sm_100)
// ---------------------------------------------------------------------------
__device__ __forceinline__ void ldsm_x4(uint32_t* a, uint32_t addr){
    asm volatile("ldmatrix.sync.aligned.m8n8.x4.shared.b16 {%0,%1,%2,%3}, [%4];"
        : "=r"(a[0]),"=r"(a[1]),"=r"(a[2]),"=r"(a[3]) : "r"(addr));
}
__device__ __forceinline__ void ldsm_x2(uint32_t* b, uint32_t addr){
    asm volatile("ldmatrix.sync.aligned.m8n8.x2.shared.b16 {%0,%1}, [%2];"
        : "=r"(b[0]),"=r"(b[1]) : "r"(addr));
}
__device__ __forceinline__ void ldsm_x2_trans(uint32_t* b, uint32_t addr){
    asm volatile("ldmatrix.sync.aligned.m8n8.x2.trans.shared.b16 {%0,%1}, [%2];"
        : "=r"(b[0]),"=r"(b[1]) : "r"(addr));
}
__device__ __forceinline__ void mma16816(float* d, const uint32_t* a, const uint32_t* b){
    asm volatile("mma.sync.aligned.m16n8k16.row.col.f32.f16.f16.f32 "
        "{%0,%1,%2,%3}, {%4,%5,%6,%7}, {%8,%9}, {%0,%1,%2,%3};"
        : "+f"(d[0]),"+f"(d[1]),"+f"(d[2]),"+f"(d[3])
        : "r"(a[0]),"r"(a[1]),"r"(a[2]),"r"(a[3]), "r"(b[0]),"r"(b[1]));
}

// ---------------------------------------------------------------------------
// Fold BN into conv weights, split into fp16 hi/lo planes; fold bias.
// ---------------------------------------------------------------------------
__global__ void fold_weights_kernel(const float* __restrict__ w,
                                    const float* __restrict__ b,
                                    const float* __restrict__ gam,
                                    const float* __restrict__ beta,
                                    const float* __restrict__ mean,
                                    const float* __restrict__ var)
{
    int idx = blockIdx.x * blockDim.x + threadIdx.x;   // 4*C*C threads
    int oc = idx >> 8;                                 // i*C + o
    float inv = gam[oc] * rsqrtf(var[oc] + 1e-5f);
    float wp = w[idx] * inv;
    __half hi = __float2half_rn(wp);
    __half lo = __float2half_rn(wp - __half2float(hi));
    g_w16h[idx] = hi;
    g_w16l[idx] = lo;
    if (idx < 4*CC){
        float invb = gam[idx] * rsqrtf(var[idx] + 1e-5f);
        g_bp[idx] = (b[idx] - mean[idx]) * invb + beta[idx];
    }
}

// ---------------------------------------------------------------------------
// tmp = query + query_pos (fp32) ; x16 = spike(tmp) fp16. Zero g_M.
// ---------------------------------------------------------------------------
__global__ void prep_kernel(const float4* __restrict__ q, const float4* __restrict__ qp)
{
    int i = blockIdx.x * blockDim.x + threadIdx.x;     // TBCN/4 threads
    float4 a = q[i], c = qp[i];
    float4 s = make_float4(a.x + c.x, a.y + c.y, a.z + c.z, a.w + c.w);
    reinterpret_cast<float4*>(g_tmp)[i] = s;
    uint2 hv = make_uint2(pack2(spikef(s.x), spikef(s.y)),
                          pack2(spikef(s.z), spikef(s.w)));
    reinterpret_cast<uint2*>(g_x16)[i] = hv;
    if (i < (64*DD*DD)/4)
        reinterpret_cast<float4*>(g_M)[i] = make_float4(0.f,0.f,0.f,0.f);
}

// ---------------------------------------------------------------------------
// HMMA GEMM. Per CTA: D[m=128, n=128] = sum_k (Whi+Wlo)[m,k] * X[k,n].
// MODE 0: qkv (src g_x16, M=768, out g_qkv fp16 split by branch, spike)
// MODE 1: proj (src g_os,  M=256, out fp32 = D + bias + residual g_tmp)
// ---------------------------------------------------------------------------
#define AS_STRIDE 72                     // halves per A row (144B: 16-aligned, %128=16)
#define BS_STRIDE 136                    // halves per B row (272B)
#define AS_BYTES (2*128*AS_STRIDE*2)     // 36864
#define BS_BYTES (64*BS_STRIDE*2)        // 17408
#define GEMM_SMEM (AS_BYTES + BS_BYTES)  // 54272

template<int MODE>
__global__ void __launch_bounds__(256, 2) mma_gemm_kernel(float* __restrict__ out)
{
    extern __shared__ __half smem[];
    __half* As = smem;                          // [2][128][AS_STRIDE]
    __half* Bs = smem + 2*128*AS_STRIDE;        // [64][BS_STRIDE]
    const int tid  = threadIdx.x;
    const int wid  = tid >> 5;
    const int lane = tid & 31;
    const int tb = blockIdx.z;
    const int bn = blockIdx.x * 128;
    const int bm = blockIdx.y * 128;
    const int WOFF = (MODE == 0) ? 0 : 768;
    const int wm = (wid & 1) * 64;              // warp m offset
    const int wn = (wid >> 1) * 32;             // warp n offset

    float acc[16][4];
#pragma unroll
    for (int i = 0; i < 16; i++)
#pragma unroll
        for (int j = 0; j < 4; j++) acc[i][j] = 0.f;

    const __half* xsrc = (MODE == 0 ? g_x16 : g_os) + tb*CN + bn;

    for (int k0 = 0; k0 < CC; k0 += 64){
        // ---- stage A (both planes), 128 rows x 64 k-halves each ----
#pragma unroll
        for (int p = 0; p < 2; p++){
            const __half* src = (p ? g_w16l : g_w16h) + (WOFF + bm)*CC + k0;
#pragma unroll
            for (int j = 0; j < 4; j++){
                int idx = tid + 256*j;          // 0..1023
                int r = idx >> 3;               // m row
                int c8 = (idx & 7) << 3;        // k offset (8 halves)
                uint4 v = *reinterpret_cast<const uint4*>(src + r*CC + c8);
                *reinterpret_cast<uint4*>(&As[(p*128 + r)*AS_STRIDE + c8]) = v;
            }
        }
        // ---- stage B: 64 k rows x 128 n halves, direct fp16 copy ----
#pragma unroll
        for (int j = 0; j < 4; j++){
            int idx = tid + 256*j;              // 0..1023
            int r = idx >> 4;                   // k row 0..63
            int c8 = (idx & 15) << 3;           // n offset (8 halves)
            uint4 v = *reinterpret_cast<const uint4*>(xsrc + (k0 + r)*NN + c8);
            *reinterpret_cast<uint4*>(&Bs[r*BS_STRIDE + c8]) = v;
        }
        __syncthreads();

        // ---- compute: 4 k16 steps ----
#pragma unroll
        for (int kk = 0; kk < 64; kk += 16){
            uint32_t bf[4][2];
#pragma unroll
            for (int nt = 0; nt < 4; nt++){
                uint32_t addr = smem_to_u32(
                    &Bs[(kk + (lane & 15))*BS_STRIDE + wn + nt*8]);
                ldsm_x2_trans(bf[nt], addr);
            }
#pragma unroll
            for (int mt = 0; mt < 4; mt++){
#pragma unroll
                for (int p = 0; p < 2; p++){
                    uint32_t af[4];
                    uint32_t addr = smem_to_u32(
                        &As[(p*128 + wm + mt*16 + (lane & 15))*AS_STRIDE
                            + kk + (lane >> 4)*8]);
                    ldsm_x4(af, addr);
#pragma unroll
                    for (int nt = 0; nt < 4; nt++)
                        mma16816(acc[mt*4 + nt], af, bf[nt]);
                }
            }
        }
        __syncthreads();
    }

    // ---- epilogue ----
#pragma unroll
    for (int mt = 0; mt < 4; mt++){
#pragma unroll
        for (int nt = 0; nt < 4; nt++){
            const float* a = acc[mt*4 + nt];
            int row = wm + mt*16 + (lane >> 2);      // 0..127 (and +8)
            int col = wn + nt*8 + ((lane & 3) << 1); // 0..126, even
            if (MODE == 0){
                int gm0 = bm + row, gm1 = gm0 + 8;
                float b0 = g_bp[gm0], b1 = g_bp[gm1];
                uint32_t v0 = pack2(spikef(a[0] + b0), spikef(a[1] + b0));
                uint32_t v1 = pack2(spikef(a[2] + b1), spikef(a[3] + b1));
                *reinterpret_cast<uint32_t*>(
                    &g_qkv[(gm0 >> 8)*TBCN + tb*CN + (gm0 & 255)*NN + bn + col]) = v0;
                *reinterpret_cast<uint32_t*>(
                    &g_qkv[(gm1 >> 8)*TBCN + tb*CN + (gm1 & 255)*NN + bn + col]) = v1;
            } else {
                int gm0 = bm + row, gm1 = gm0 + 8;
                float b0 = g_bp[768 + gm0], b1 = g_bp[768 + gm1];
                int i0 = tb*CN + gm0*NN + bn + col;
                int i1 = tb*CN + gm1*NN + bn + col;
                float2 r0 = *reinterpret_cast<const float2*>(&g_tmp[i0]);
                float2 r1 = *reinterpret_cast<const float2*>(&g_tmp[i1]);
                float2 v0 = make_float2(a[0] + b0 + r0.x, a[1] + b0 + r0.y);
                float2 v1 = make_float2(a[2] + b1 + r1.x, a[3] + b1 + r1.y);
                *reinterpret_cast<float2*>(&out[i0]) = v0;
                *reinterpret_cast<float2*>(&out[i1]) = v1;
            }
        }
    }
}

// ---------------------------------------------------------------------------
// Attention phase 1 (HMMA, n-split): partial M[e,d] over one 128-n chunk.
// grid 512 = 64 heads x 8 chunks. Each warp takes a 16-wide k-slice (one MMA
// round), cross-warp smem reduce, atomicAdd into fp32 g_M (exact: partials
// are multiples of 1/16, order-independent).
// ---------------------------------------------------------------------------
#define KV_STRIDE 136
__global__ void __launch_bounds__(256) kv_kernel()
{
    __shared__ __align__(16) char sbuf[32768];
    __half (*Ks)[KV_STRIDE] = reinterpret_cast<__half(*)[KV_STRIDE]>(sbuf);
    __half (*Vs)[KV_STRIDE] = reinterpret_cast<__half(*)[KV_STRIDE]>(sbuf + 32*KV_STRIDE*2);
    float (*red)[1024] = reinterpret_cast<float(*)[1024]>(sbuf);   // aliases Ks/Vs

    const int hh = blockIdx.x >> 3;              // 0..63
    const int nb = (blockIdx.x & 7) << 7;        // n chunk base
    const int tid = threadIdx.x;
    const int wid = tid >> 5;
    const int lane = tid & 31;
    const __half* K = g_qkv + TBCN   + hh*DD*NN;
    const __half* V = g_qkv + 2*TBCN + hh*DD*NN;

    // load K,V 32 x 128 chunk
#pragma unroll
    for (int j = 0; j < 2; j++){
        int idx = tid + 256*j;                   // 0..511
        int r = idx >> 4;                        // row 0..31
        int c8 = (idx & 15) << 3;                // 0..120
        *reinterpret_cast<uint4*>(&Ks[r][c8]) =
            *reinterpret_cast<const uint4*>(&K[r*NN + nb + c8]);
        *reinterpret_cast<uint4*>(&Vs[r][c8]) =
            *reinterpret_cast<const uint4*>(&V[r*NN + nb + c8]);
    }
    __syncthreads();

    float acc[2][4][4];
#pragma unroll
    for (int mt = 0; mt < 2; mt++)
#pragma unroll
        for (int nt = 0; nt < 4; nt++)
#pragma unroll
            for (int i = 0; i < 4; i++) acc[mt][nt][i] = 0.f;

    const int kslice = wid * 16;
    uint32_t a0[4], a1[4];
    ldsm_x4(a0, smem_to_u32(&Ks[lane & 15][kslice + (lane >> 4)*8]));
    ldsm_x4(a1, smem_to_u32(&Ks[16 + (lane & 15)][kslice + (lane >> 4)*8]));
#pragma unroll
    for (int nt = 0; nt < 4; nt++){
        uint32_t bf[2];
        ldsm_x2(bf, smem_to_u32(&Vs[nt*8 + (lane & 7)][kslice + ((lane >> 3) & 1)*8]));
        mma16816(acc[0][nt], a0, bf);
        mma16816(acc[1][nt], a1, bf);
    }
    __syncthreads();

    // ---- cross-warp reduction (red aliases Ks/Vs) ----
#pragma unroll
    for (int mt = 0; mt < 2; mt++)
#pragma unroll
        for (int nt = 0; nt < 4; nt++)
#pragma unroll
            for (int i = 0; i < 4; i++){
                int e = mt*16 + (lane >> 2) + ((i >= 2) ? 8 : 0);
                int d = nt*8 + ((lane & 3) << 1) + (i & 1);
                red[wid][e*32 + d] = acc[mt][nt][i];
            }
    __syncthreads();
#pragma unroll
    for (int i = 0; i < 4; i++){
        int j = tid*4 + i;                       // j = e*32 + d
        float s = red[0][j] + red[1][j] + red[2][j] + red[3][j]
                + red[4][j] + red[5][j] + red[6][j] + red[7][j];
        atomicAdd(&g_M[hh*1024 + j], s);
    }
}

// ---------------------------------------------------------------------------
// Attention phase 2 (HMMA, n-split): O[d,n] = spike(0.1*sum_e M[e,d]*Q[e,n]).
// 256 CTAs = 64 heads x 4 x 256-n chunks. Per CTA: load g_M fp32, split into
// exact fp16 hi/lo tiles [d][e] in smem; A = M^T hi/lo, B = Q (trans ldsm).
// 8 warps x 32-n windows.
// ---------------------------------------------------------------------------
#define QS_STRIDE 264
__global__ void __launch_bounds__(256) qm_kernel()
{
    __shared__ __align__(16) __half Qs[32][QS_STRIDE];
    __shared__ __align__(16) __half Mh[32][40];
    __shared__ __align__(16) __half Ml[32][40];
    const int hh = blockIdx.x >> 2;
    const int nb = (blockIdx.x & 3) << 8;        // 0,256,512,768
    const int tid = threadIdx.x;
    const int wid = tid >> 5;
    const int lane = tid & 31;
    const int cbase = hh * (DD*NN);
    const __half* Q = g_qkv + cbase;

    // load M fp32 [e][d] -> exact hi/lo fp16 smem tiles [d][e]
#pragma unroll
    for (int i = tid; i < 1024; i += 256){
        float s = g_M[hh*1024 + i];
        __half hi = __float2half_rn(s);
        __half lo = __float2half_rn(s - __half2float(hi));
        int e = i >> 5, d = i & 31;
        Mh[d][e] = hi;
        Ml[d][e] = lo;
    }
    // load Q chunk [32 e][256 n]
#pragma unroll
    for (int j = 0; j < 4; j++){
        int idx = tid + 256*j;                   // 0..1023
        int r = idx >> 5;                        // e row 0..31
        int c8 = (idx & 31) << 3;                // 0..248
        *reinterpret_cast<uint4*>(&Qs[r][c8]) =
            *reinterpret_cast<const uint4*>(&Q[r*NN + nb + c8]);
    }
    __syncthreads();

    const int wn = wid * 32;
    float acc[2][4][4];
#pragma unroll
    for (int mt = 0; mt < 2; mt++)
#pragma unroll
        for (int nt = 0; nt < 4; nt++)
#pragma unroll
            for (int i = 0; i < 4; i++) acc[mt][nt][i] = 0.f;

#pragma unroll
    for (int e0 = 0; e0 < 32; e0 += 16){
        uint32_t bf[4][2];
#pragma unroll
        for (int nt = 0; nt < 4; nt++)
            ldsm_x2_trans(bf[nt],
                smem_to_u32(&Qs[e0 + (lane & 15)][wn + nt*8]));
#pragma unroll
        for (int mt = 0; mt < 2; mt++){
            uint32_t ah[4], al[4];
            ldsm_x4(ah, smem_to_u32(&Mh[mt*16 + (lane & 15)][e0 + (lane >> 4)*8]));
            ldsm_x4(al, smem_to_u32(&Ml[mt*16 + (lane & 15)][e0 + (lane >> 4)*8]));
#pragma unroll
            for (int nt = 0; nt < 4; nt++){
                mma16816(acc[mt][nt], ah, bf[nt]);
                mma16816(acc[mt][nt], al, bf[nt]);
            }
        }
    }

    // epilogue: spike(0.1*O) -> g_os fp16
#pragma unroll
    for (int mt = 0; mt < 2; mt++){
#pragma unroll
        for (int nt = 0; nt < 4; nt++){
            const float* a = acc[mt][nt];
            int d0 = mt*16 + (lane >> 2);
            int n  = nb + wn + nt*8 + ((lane & 3) << 1);
            uint32_t v0 = pack2(spikef(0.1f*a[0]), spikef(0.1f*a[1]));
            uint32_t v1 = pack2(spikef(0.1f*a[2]), spikef(0.1f*a[3]));
            *reinterpret_cast<uint32_t*>(&g_os[cbase + d0*NN + n]) = v0;
            *reinterpret_cast<uint32_t*>(&g_os[cbase + (d0+8)*NN + n]) = v1;
        }
    }
}

// ---------------------------------------------------------------------------
extern "C" void kernel_launch(void* const* d_in, const int* in_sizes, int n_in,
                              void* d_out, int out_size)
{
    const float* q    = (const float*)d_in[0];
    // d_in[1] (key) and d_in[2] (value) are unused by the reference
    const float* qp   = (const float*)d_in[3];
    const float* w    = (const float*)d_in[4];
    const float* b    = (const float*)d_in[5];
    const float* gam  = (const float*)d_in[6];
    const float* bet  = (const float*)d_in[7];
    const float* mean = (const float*)d_in[8];
    const float* var  = (const float*)d_in[9];
    float* out = (float*)d_out;

    cudaFuncSetAttribute(mma_gemm_kernel<0>,
                         cudaFuncAttributeMaxDynamicSharedMemorySize, GEMM_SMEM);
    cudaFuncSetAttribute(mma_gemm_kernel<1>,
                         cudaFuncAttributeMaxDynamicSharedMemorySize, GEMM_SMEM);

    fold_weights_kernel<<<(4*CC*CC)/256, 256>>>(w, b, gam, bet, mean, var);
    prep_kernel<<<(TBCN/4)/256, 256>>>((const float4*)q, (const float4*)qp);

    dim3 gq(NN/128, 768/128, TB);   // 8 x 6 x 8 = 384 CTAs
    mma_gemm_kernel<0><<<gq, 256, GEMM_SMEM>>>(nullptr);

    kv_kernel<<<512, 256>>>();
    qm_kernel<<<256, 256>>>();

    dim3 gp(NN/128, CC/128, TB);    // 8 x 2 x 8 = 128 CTAs
    mma_gemm_kernel<1><<<gp, 256, GEMM_SMEM>>>(out);
}

// round 12
// speedup vs baseline: 2.9682x; 1.0005x over previous
#include <cuda_runtime.h>
#include <cuda_fp16.h>
#include <math.h>
#include <cstdint>

#define TT 4
#define BB 2
#define TB 8
#define NN 1024
#define CC 256
#define HH 8
#define DD 32
#define CN (CC*NN)        // 262144
#define TBCN (TB*CN)      // 2097152

// ---------------------------------------------------------------------------
// Scratch (static device globals: no allocations allowed)
// ---------------------------------------------------------------------------
__device__ float g_tmp[TBCN];                        // query + query_pos (fp32, residual)
__device__ __align__(16) __half g_x16[TBCN];         // spike(tmp) fp16 (qkv GEMM input)
__device__ __align__(16) __half g_qkv[3*TBCN];       // spiked q,k,v fp16 (TB,C,N)
__device__ __align__(16) __half g_os[TBCN];          // spiked attention output fp16
__device__ __align__(16) __half g_Mp[64*8*1024];     // per-(head,chunk) K^T V partials fp16 (exact)
__device__ __align__(16) __half g_w16h[4*CC*CC];     // BN-folded weights hi
__device__ __align__(16) __half g_w16l[4*CC*CC];     // BN-folded weights lo
__device__ float g_bp[4*CC];                         // BN-folded biases

// MultiSpike_norm4: round(clamp(x,0,4))/4 ; jnp.round = round-half-even = rintf
__device__ __forceinline__ float spikef(float v){
    v = fminf(fmaxf(v, 0.0f), 4.0f);
    return rintf(v) * 0.25f;
}

__device__ __forceinline__ uint32_t pack2(float a, float b){
    __half2 h = __halves2half2(__float2half_rn(a), __float2half_rn(b));
    return *reinterpret_cast<uint32_t*>(&h);
}

__device__ __forceinline__ uint32_t smem_to_u32(const void* p) {
    uint32_t a;
    asm("{ .reg .u64 t; cvta.to.shared.u64 t, %1; cvt.u32.u64 %0, t; }"
        : "=r"(a) : "l"(p));
    return a;
}

// ---------------------------------------------------------------------------
// Warp MMA primitives (baseline PTX, works on .target sm_100)
// ---------------------------------------------------------------------------
__device__ __forceinline__ void ldsm_x4(uint32_t* a, uint32_t addr){
    asm volatile("ldmatrix.sync.aligned.m8n8.x4.shared.b16 {%0,%1,%2,%3}, [%4];"
        : "=r"(a[0]),"=r"(a[1]),"=r"(a[2]),"=r"(a[3]) : "r"(addr));
}
__device__ __forceinline__ void ldsm_x2(uint32_t* b, uint32_t addr){
    asm volatile("ldmatrix.sync.aligned.m8n8.x2.shared.b16 {%0,%1}, [%2];"
        : "=r"(b[0]),"=r"(b[1]) : "r"(addr));
}
__device__ __forceinline__ void ldsm_x2_trans(uint32_t* b, uint32_t addr){
    asm volatile("ldmatrix.sync.aligned.m8n8.x2.trans.shared.b16 {%0,%1}, [%2];"
        : "=r"(b[0]),"=r"(b[1]) : "r"(addr));
}
__device__ __forceinline__ void mma16816(float* d, const uint32_t* a, const uint32_t* b){
    asm volatile("mma.sync.aligned.m16n8k16.row.col.f32.f16.f16.f32 "
        "{%0,%1,%2,%3}, {%4,%5,%6,%7}, {%8,%9}, {%0,%1,%2,%3};"
        : "+f"(d[0]),"+f"(d[1]),"+f"(d[2]),"+f"(d[3])
        : "r"(a[0]),"r"(a[1]),"r"(a[2]),"r"(a[3]), "r"(b[0]),"r"(b[1]));
}

// ---------------------------------------------------------------------------
// prep (+ merged weight fold):
//   all 2048 CTAs: tmp = q + qp (fp32); x16 = spike(tmp) fp16.
//   CTAs 0..1023 additionally fold one weight element per thread.
// ---------------------------------------------------------------------------
__global__ void prep_kernel(const float4* __restrict__ q, const float4* __restrict__ qp,
                            const float* __restrict__ w,
                            const float* __restrict__ b,
                            const float* __restrict__ gam,
                            const float* __restrict__ beta,
                            const float* __restrict__ mean,
                            const float* __restrict__ var)
{
    int i = blockIdx.x * blockDim.x + threadIdx.x;     // TBCN/4 threads
    float4 a = q[i], c = qp[i];
    float4 s = make_float4(a.x + c.x, a.y + c.y, a.z + c.z, a.w + c.w);
    reinterpret_cast<float4*>(g_tmp)[i] = s;
    uint2 hv = make_uint2(pack2(spikef(s.x), spikef(s.y)),
                          pack2(spikef(s.z), spikef(s.w)));
    reinterpret_cast<uint2*>(g_x16)[i] = hv;

    if (i < 4*CC*CC){
        int oc = i >> 8;                               // i*C + o
        float inv = gam[oc] * rsqrtf(var[oc] + 1e-5f);
        float wp = w[i] * inv;
        __half hi = __float2half_rn(wp);
        __half lo = __float2half_rn(wp - __half2float(hi));
        g_w16h[i] = hi;
        g_w16l[i] = lo;
        if (i < 4*CC){
            float invb = gam[i] * rsqrtf(var[i] + 1e-5f);
            g_bp[i] = (b[i] - mean[i]) * invb + beta[i];
        }
    }
}

// ---------------------------------------------------------------------------
// HMMA GEMM. Per CTA: D[m=128, n=128] = sum_k (Whi+Wlo)[m,k] * X[k,n].
// MODE 0: qkv (src g_x16, M=768, out g_qkv fp16 split by branch, spike)
// MODE 1: proj (src g_os,  M=256, out fp32 = D + bias + residual g_tmp)
// ---------------------------------------------------------------------------
#define AS_STRIDE 72                     // halves per A row (144B: 16-aligned, %128=16)
#define BS_STRIDE 136                    // halves per B row (272B)
#define AS_BYTES (2*128*AS_STRIDE*2)     // 36864
#define BS_BYTES (64*BS_STRIDE*2)        // 17408
#define GEMM_SMEM (AS_BYTES + BS_BYTES)  // 54272

template<int MODE>
__global__ void __launch_bounds__(256, 2) mma_gemm_kernel(float* __restrict__ out)
{
    extern __shared__ __half smem[];
    __half* As = smem;                          // [2][128][AS_STRIDE]
    __half* Bs = smem + 2*128*AS_STRIDE;        // [64][BS_STRIDE]
    const int tid  = threadIdx.x;
    const int wid  = tid >> 5;
    const int lane = tid & 31;
    const int tb = blockIdx.z;
    const int bn = blockIdx.x * 128;
    const int bm = blockIdx.y * 128;
    const int WOFF = (MODE == 0) ? 0 : 768;
    const int wm = (wid & 1) * 64;              // warp m offset
    const int wn = (wid >> 1) * 32;             // warp n offset

    float acc[16][4];
#pragma unroll
    for (int i = 0; i < 16; i++)
#pragma unroll
        for (int j = 0; j < 4; j++) acc[i][j] = 0.f;

    const __half* xsrc = (MODE == 0 ? g_x16 : g_os) + tb*CN + bn;

    for (int k0 = 0; k0 < CC; k0 += 64){
        // ---- stage A (both planes), 128 rows x 64 k-halves each ----
#pragma unroll
        for (int p = 0; p < 2; p++){
            const __half* src = (p ? g_w16l : g_w16h) + (WOFF + bm)*CC + k0;
#pragma unroll
            for (int j = 0; j < 4; j++){
                int idx = tid + 256*j;          // 0..1023
                int r = idx >> 3;               // m row
                int c8 = (idx & 7) << 3;        // k offset (8 halves)
                uint4 v = *reinterpret_cast<const uint4*>(src + r*CC + c8);
                *reinterpret_cast<uint4*>(&As[(p*128 + r)*AS_STRIDE + c8]) = v;
            }
        }
        // ---- stage B: 64 k rows x 128 n halves, direct fp16 copy ----
#pragma unroll
        for (int j = 0; j < 4; j++){
            int idx = tid + 256*j;              // 0..1023
            int r = idx >> 4;                   // k row 0..63
            int c8 = (idx & 15) << 3;           // n offset (8 halves)
            uint4 v = *reinterpret_cast<const uint4*>(xsrc + (k0 + r)*NN + c8);
            *reinterpret_cast<uint4*>(&Bs[r*BS_STRIDE + c8]) = v;
        }
        __syncthreads();

        // ---- compute: 4 k16 steps ----
#pragma unroll
        for (int kk = 0; kk < 64; kk += 16){
            uint32_t bf[4][2];
#pragma unroll
            for (int nt = 0; nt < 4; nt++){
                uint32_t addr = smem_to_u32(
                    &Bs[(kk + (lane & 15))*BS_STRIDE + wn + nt*8]);
                ldsm_x2_trans(bf[nt], addr);
            }
#pragma unroll
            for (int mt = 0; mt < 4; mt++){
#pragma unroll
                for (int p = 0; p < 2; p++){
                    uint32_t af[4];
                    uint32_t addr = smem_to_u32(
                        &As[(p*128 + wm + mt*16 + (lane & 15))*AS_STRIDE
                            + kk + (lane >> 4)*8]);
                    ldsm_x4(af, addr);
#pragma unroll
                    for (int nt = 0; nt < 4; nt++)
                        mma16816(acc[mt*4 + nt], af, bf[nt]);
                }
            }
        }
        __syncthreads();
    }

    // ---- epilogue ----
#pragma unroll
    for (int mt = 0; mt < 4; mt++){
#pragma unroll
        for (int nt = 0; nt < 4; nt++){
            const float* a = acc[mt*4 + nt];
            int row = wm + mt*16 + (lane >> 2);      // 0..127 (and +8)
            int col = wn + nt*8 + ((lane & 3) << 1); // 0..126, even
            if (MODE == 0){
                int gm0 = bm + row, gm1 = gm0 + 8;
                float b0 = g_bp[gm0], b1 = g_bp[gm1];
                uint32_t v0 = pack2(spikef(a[0] + b0), spikef(a[1] + b0));
                uint32_t v1 = pack2(spikef(a[2] + b1), spikef(a[3] + b1));
                *reinterpret_cast<uint32_t*>(
                    &g_qkv[(gm0 >> 8)*TBCN + tb*CN + (gm0 & 255)*NN + bn + col]) = v0;
                *reinterpret_cast<uint32_t*>(
                    &g_qkv[(gm1 >> 8)*TBCN + tb*CN + (gm1 & 255)*NN + bn + col]) = v1;
            } else {
                int gm0 = bm + row, gm1 = gm0 + 8;
                float b0 = g_bp[768 + gm0], b1 = g_bp[768 + gm1];
                int i0 = tb*CN + gm0*NN + bn + col;
                int i1 = tb*CN + gm1*NN + bn + col;
                float2 r0 = *reinterpret_cast<const float2*>(&g_tmp[i0]);
                float2 r1 = *reinterpret_cast<const float2*>(&g_tmp[i1]);
                float2 v0 = make_float2(a[0] + b0 + r0.x, a[1] + b0 + r0.y);
                float2 v1 = make_float2(a[2] + b1 + r1.x, a[3] + b1 + r1.y);
                *reinterpret_cast<float2*>(&out[i0]) = v0;
                *reinterpret_cast<float2*>(&out[i1]) = v1;
            }
        }
    }
}

// ---------------------------------------------------------------------------
// Attention phase 1 (HMMA, n-split): partial M[e,d] over one 128-n chunk.
// grid 512 = 64 heads x 8 chunks. Cross-warp smem reduce, then PLAIN fp16
// stores into g_Mp[hh][chunk] — exact (partials are multiples of 1/16, <=128
// => <=2^11 units, exact in fp16). No atomics.
// ---------------------------------------------------------------------------
#define KV_STRIDE 136
__global__ void __launch_bounds__(256) kv_kernel()
{
    __shared__ __align__(16) char sbuf[32768];
    __half (*Ks)[KV_STRIDE] = reinterpret_cast<__half(*)[KV_STRIDE]>(sbuf);
    __half (*Vs)[KV_STRIDE] = reinterpret_cast<__half(*)[KV_STRIDE]>(sbuf + 32*KV_STRIDE*2);
    float (*red)[1024] = reinterpret_cast<float(*)[1024]>(sbuf);   // aliases Ks/Vs

    const int hh = blockIdx.x >> 3;              // 0..63
    const int ch = blockIdx.x & 7;               // chunk 0..7
    const int nb = ch << 7;                      // n chunk base
    const int tid = threadIdx.x;
    const int wid = tid >> 5;
    const int lane = tid & 31;
    const __half* K = g_qkv + TBCN   + hh*DD*NN;
    const __half* V = g_qkv + 2*TBCN + hh*DD*NN;

    // load K,V 32 x 128 chunk
#pragma unroll
    for (int j = 0; j < 2; j++){
        int idx = tid + 256*j;                   // 0..511
        int r = idx >> 4;                        // row 0..31
        int c8 = (idx & 15) << 3;                // 0..120
        *reinterpret_cast<uint4*>(&Ks[r][c8]) =
            *reinterpret_cast<const uint4*>(&K[r*NN + nb + c8]);
        *reinterpret_cast<uint4*>(&Vs[r][c8]) =
            *reinterpret_cast<const uint4*>(&V[r*NN + nb + c8]);
    }
    __syncthreads();

    float acc[2][4][4];
#pragma unroll
    for (int mt = 0; mt < 2; mt++)
#pragma unroll
        for (int nt = 0; nt < 4; nt++)
#pragma unroll
            for (int i = 0; i < 4; i++) acc[mt][nt][i] = 0.f;

    const int kslice = wid * 16;
    uint32_t a0[4], a1[4];
    ldsm_x4(a0, smem_to_u32(&Ks[lane & 15][kslice + (lane >> 4)*8]));
    ldsm_x4(a1, smem_to_u32(&Ks[16 + (lane & 15)][kslice + (lane >> 4)*8]));
#pragma unroll
    for (int nt = 0; nt < 4; nt++){
        uint32_t bf[2];
        ldsm_x2(bf, smem_to_u32(&Vs[nt*8 + (lane & 7)][kslice + ((lane >> 3) & 1)*8]));
        mma16816(acc[0][nt], a0, bf);
        mma16816(acc[1][nt], a1, bf);
    }
    __syncthreads();

    // ---- cross-warp reduction (red aliases Ks/Vs) ----
#pragma unroll
    for (int mt = 0; mt < 2; mt++)
#pragma unroll
        for (int nt = 0; nt < 4; nt++)
#pragma unroll
            for (int i = 0; i < 4; i++){
                int e = mt*16 + (lane >> 2) + ((i >= 2) ? 8 : 0);
                int d = nt*8 + ((lane & 3) << 1) + (i & 1);
                red[wid][e*32 + d] = acc[mt][nt][i];
            }
    __syncthreads();
    // 1024 sums -> fp16 exact partial store (coalesced, 2 per thread as half2)
#pragma unroll
    for (int i = 0; i < 2; i++){
        int j = tid*2 + i*512;                   // two half-sized sweeps keep stores wide
        // j covers 0..511 then 512..1023
        float s = red[0][j] + red[1][j] + red[2][j] + red[3][j]
                + red[4][j] + red[5][j] + red[6][j] + red[7][j];
        g_Mp[(hh*8 + ch)*1024 + j] = __float2half_rn(s);    // exact
    }
}

// ---------------------------------------------------------------------------
// Attention phase 2 (HMMA, n-split): O[d,n] = spike(0.1*sum_e M[e,d]*Q[e,n]).
// 256 CTAs = 64 heads x 4 x 256-n chunks. Per CTA: sum the 8 fp16 partials
// (exact in fp32), split into exact fp16 hi/lo tiles [d][e] in smem;
// A = M^T hi/lo, B = Q (trans ldsm). 8 warps x 32-n windows.
// ---------------------------------------------------------------------------
#define QS_STRIDE 264
__global__ void __launch_bounds__(256) qm_kernel()
{
    __shared__ __align__(16) __half Qs[32][QS_STRIDE];
    __shared__ __align__(16) __half Mh[32][40];
    __shared__ __align__(16) __half Ml[32][40];
    const int hh = blockIdx.x >> 2;
    const int nb = (blockIdx.x & 3) << 8;        // 0,256,512,768
    const int tid = threadIdx.x;
    const int wid = tid >> 5;
    const int lane = tid & 31;
    const int cbase = hh * (DD*NN);
    const __half* Q = g_qkv + cbase;

    // sum 8 fp16 partials (exact in fp32) -> exact hi/lo fp16 smem tiles [d][e]
#pragma unroll
    for (int i = tid; i < 1024; i += 256){
        const __half* mp = g_Mp + hh*8192 + i;
        float s = 0.f;
#pragma unroll
        for (int c = 0; c < 8; c++) s += __half2float(mp[c*1024]);
        __half hi = __float2half_rn(s);
        __half lo = __float2half_rn(s - __half2float(hi));
        int e = i >> 5, d = i & 31;
        Mh[d][e] = hi;
        Ml[d][e] = lo;
    }
    // load Q chunk [32 e][256 n]
#pragma unroll
    for (int j = 0; j < 4; j++){
        int idx = tid + 256*j;                   // 0..1023
        int r = idx >> 5;                        // e row 0..31
        int c8 = (idx & 31) << 3;                // 0..248
        *reinterpret_cast<uint4*>(&Qs[r][c8]) =
            *reinterpret_cast<const uint4*>(&Q[r*NN + nb + c8]);
    }
    __syncthreads();

    const int wn = wid * 32;
    float acc[2][4][4];
#pragma unroll
    for (int mt = 0; mt < 2; mt++)
#pragma unroll
        for (int nt = 0; nt < 4; nt++)
#pragma unroll
            for (int i = 0; i < 4; i++) acc[mt][nt][i] = 0.f;

#pragma unroll
    for (int e0 = 0; e0 < 32; e0 += 16){
        uint32_t bf[4][2];
#pragma unroll
        for (int nt = 0; nt < 4; nt++)
            ldsm_x2_trans(bf[nt],
                smem_to_u32(&Qs[e0 + (lane & 15)][wn + nt*8]));
#pragma unroll
        for (int mt = 0; mt < 2; mt++){
            uint32_t ah[4], al[4];
            ldsm_x4(ah, smem_to_u32(&Mh[mt*16 + (lane & 15)][e0 + (lane >> 4)*8]));
            ldsm_x4(al, smem_to_u32(&Ml[mt*16 + (lane & 15)][e0 + (lane >> 4)*8]));
#pragma unroll
            for (int nt = 0; nt < 4; nt++){
                mma16816(acc[mt][nt], ah, bf[nt]);
                mma16816(acc[mt][nt], al, bf[nt]);
            }
        }
    }

    // epilogue: spike(0.1*O) -> g_os fp16
#pragma unroll
    for (int mt = 0; mt < 2; mt++){
#pragma unroll
        for (int nt = 0; nt < 4; nt++){
            const float* a = acc[mt][nt];
            int d0 = mt*16 + (lane >> 2);
            int n  = nb + wn + nt*8 + ((lane & 3) << 1);
            uint32_t v0 = pack2(spikef(0.1f*a[0]), spikef(0.1f*a[1]));
            uint32_t v1 = pack2(spikef(0.1f*a[2]), spikef(0.1f*a[3]));
            *reinterpret_cast<uint32_t*>(&g_os[cbase + d0*NN + n]) = v0;
            *reinterpret_cast<uint32_t*>(&g_os[cbase + (d0+8)*NN + n]) = v1;
        }
    }
}

// ---------------------------------------------------------------------------
extern "C" void kernel_launch(void* const* d_in, const int* in_sizes, int n_in,
                              void* d_out, int out_size)
{
    const float* q    = (const float*)d_in[0];
    // d_in[1] (key) and d_in[2] (value) are unused by the reference
    const float* qp   = (const float*)d_in[3];
    const float* w    = (const float*)d_in[4];
    const float* b    = (const float*)d_in[5];
    const float* gam  = (const float*)d_in[6];
    const float* bet  = (const float*)d_in[7];
    const float* mean = (const float*)d_in[8];
    const float* var  = (const float*)d_in[9];
    float* out = (float*)d_out;

    cudaFuncSetAttribute(mma_gemm_kernel<0>,
                         cudaFuncAttributeMaxDynamicSharedMemorySize, GEMM_SMEM);
    cudaFuncSetAttribute(mma_gemm_kernel<1>,
                         cudaFuncAttributeMaxDynamicSharedMemorySize, GEMM_SMEM);

    prep_kernel<<<(TBCN/4)/256, 256>>>((const float4*)q, (const float4*)qp,
                                       w, b, gam, bet, mean, var);

    dim3 gq(NN/128, 768/128, TB);   // 8 x 6 x 8 = 384 CTAs
    mma_gemm_kernel<0><<<gq, 256, GEMM_SMEM>>>(nullptr);

    kv_kernel<<<512, 256>>>();
    qm_kernel<<<256, 256>>>();

    dim3 gp(NN/128, CC/128, TB);    // 8 x 2 x 8 = 128 CTAs
    mma_gemm_kernel<1><<<gp, 256, GEMM_SMEM>>>(out);
}